// round 1
// baseline (speedup 1.0000x reference)
#include <cuda_runtime.h>
#include <cuda_bf16.h>
#include <math.h>
#include <stdint.h>

// Problem constants
#define H_HEADS 25
#define B_DIM   8
#define N_TOK   1025
#define C_DIM   3200
#define D_HEAD  128
#define M_ROWS  (B_DIM * N_TOK)   // 8200
#define SD      1028              // padded stride for score rows (16B aligned)

// Scratch (device globals: allocation inside kernel_launch is forbidden)
__device__ float g_qkv[(size_t)M_ROWS * 3 * C_DIM];               // [8200, 9600]
__device__ float g_S[(size_t)B_DIM * H_HEADS * N_TOK * SD];       // [200, 1025, 1028]
__device__ float g_att[(size_t)M_ROWS * C_DIM];                   // [8200, 3200]

__device__ __forceinline__ float f2tf32(float x) {
    float r;
    asm("cvt.rna.tf32.f32 %0, %1;" : "=f"(r) : "f"(x));
    return r;
}

__device__ __forceinline__ void mma_tf32(float (&d)[4], const unsigned (&a)[4], const unsigned (&b)[2]) {
    asm volatile(
        "mma.sync.aligned.m16n8k8.row.col.f32.tf32.tf32.f32 "
        "{%0,%1,%2,%3}, {%4,%5,%6,%7}, {%8,%9}, {%0,%1,%2,%3};"
        : "+f"(d[0]), "+f"(d[1]), "+f"(d[2]), "+f"(d[3])
        : "r"(a[0]), "r"(a[1]), "r"(a[2]), "r"(a[3]), "r"(b[0]), "r"(b[1]));
}

// Generic batched TF32 GEMM: C = alpha*A (MxK) * B + bias
// TRANS_B=false: B is [K,N] row-major.  TRANS_B=true: B is [N,K] row-major.
// Batch offset for operand X: (z / binner)*Xso + (z % binner)*Xsi.
// Block tile 128x128x32, 256 threads, warp tile 64x32 (2x4 warps), m16n8k8.
template<bool TRANS_B>
__global__ void __launch_bounds__(256, 2)
gemm_tf32(const float* __restrict__ A, const float* __restrict__ B,
          const float* __restrict__ bias, float* __restrict__ C,
          int M, int N, int K,
          long lda, long ldb, long ldc,
          long aso, long asi, long bso, long bsi, long cso, long csi,
          int binner, float alpha)
{
    __shared__ float As[128 * 36];   // [m][k], stride 36 (16B aligned, conflict-free frag reads)
    __shared__ float Bs[32 * 132];   // [k][n], stride 132

    int z = blockIdx.z;
    int zo = z / binner, zi = z - zo * binner;
    A += (long)zo * aso + (long)zi * asi;
    B += (long)zo * bso + (long)zi * bsi;
    C += (long)zo * cso + (long)zi * csi;

    const int bm0 = blockIdx.y * 128;
    const int bn0 = blockIdx.x * 128;
    const int tid = threadIdx.x;
    const int lane = tid & 31, warp = tid >> 5;
    const int wm = warp & 1, wn = warp >> 1;   // 2 x 4 warp grid
    const int lr = lane >> 2, lc = lane & 3;

    float acc[4][4][4];
    #pragma unroll
    for (int mi = 0; mi < 4; mi++)
        #pragma unroll
        for (int ni = 0; ni < 4; ni++)
            #pragma unroll
            for (int r = 0; r < 4; r++)
                acc[mi][ni][r] = 0.f;

    for (int k0 = 0; k0 < K; k0 += 32) {
        // ---- Load A tile (128 x 32) ----
        #pragma unroll
        for (int i = 0; i < 4; i++) {
            int f = tid + i * 256;
            int row = f >> 3, kq = (f & 7) * 4;
            int gm = bm0 + row, gk = k0 + kq;
            float4 v = make_float4(0.f, 0.f, 0.f, 0.f);
            if (gm < M && gk < K)
                v = *reinterpret_cast<const float4*>(A + (long)gm * lda + gk);
            v.x = f2tf32(v.x * alpha); v.y = f2tf32(v.y * alpha);
            v.z = f2tf32(v.z * alpha); v.w = f2tf32(v.w * alpha);
            *reinterpret_cast<float4*>(&As[row * 36 + kq]) = v;
        }
        // ---- Load B tile into Bs[k][n] (32 x 128) ----
        if (!TRANS_B) {
            #pragma unroll
            for (int i = 0; i < 4; i++) {
                int f = tid + i * 256;
                int kr = f >> 5, nq = (f & 31) * 4;
                int gk = k0 + kr, gn = bn0 + nq;
                float4 v = make_float4(0.f, 0.f, 0.f, 0.f);
                if (gk < K && gn < N)
                    v = *reinterpret_cast<const float4*>(B + (long)gk * ldb + gn);
                v.x = f2tf32(v.x); v.y = f2tf32(v.y);
                v.z = f2tf32(v.z); v.w = f2tf32(v.w);
                *reinterpret_cast<float4*>(&Bs[kr * 132 + nq]) = v;
            }
        } else {
            #pragma unroll
            for (int i = 0; i < 4; i++) {
                int f = tid + i * 256;
                int nrow = f >> 3, kq = (f & 7) * 4;
                int gn = bn0 + nrow, gk = k0 + kq;
                float4 v = make_float4(0.f, 0.f, 0.f, 0.f);
                if (gn < N && gk < K)
                    v = *reinterpret_cast<const float4*>(B + (long)gn * ldb + gk);
                Bs[(kq + 0) * 132 + nrow] = f2tf32(v.x);
                Bs[(kq + 1) * 132 + nrow] = f2tf32(v.y);
                Bs[(kq + 2) * 132 + nrow] = f2tf32(v.z);
                Bs[(kq + 3) * 132 + nrow] = f2tf32(v.w);
            }
        }
        __syncthreads();

        // ---- Compute: 4 k8 steps, 16 mma each ----
        #pragma unroll
        for (int ks = 0; ks < 4; ks++) {
            unsigned af[4][4], bf[4][2];
            #pragma unroll
            for (int mi = 0; mi < 4; mi++) {
                const float* p = &As[(wm * 64 + mi * 16 + lr) * 36 + ks * 8 + lc];
                af[mi][0] = __float_as_uint(p[0]);
                af[mi][1] = __float_as_uint(p[8 * 36]);
                af[mi][2] = __float_as_uint(p[4]);
                af[mi][3] = __float_as_uint(p[8 * 36 + 4]);
            }
            #pragma unroll
            for (int ni = 0; ni < 4; ni++) {
                const float* p = &Bs[(ks * 8 + lc) * 132 + wn * 32 + ni * 8 + lr];
                bf[ni][0] = __float_as_uint(p[0]);
                bf[ni][1] = __float_as_uint(p[4 * 132]);
            }
            #pragma unroll
            for (int mi = 0; mi < 4; mi++)
                #pragma unroll
                for (int ni = 0; ni < 4; ni++)
                    mma_tf32(acc[mi][ni], af[mi], bf[ni]);
        }
        __syncthreads();
    }

    // ---- Epilogue ----
    #pragma unroll
    for (int mi = 0; mi < 4; mi++) {
        #pragma unroll
        for (int ni = 0; ni < 4; ni++) {
            int r0 = bm0 + wm * 64 + mi * 16 + lr;
            int c0 = bn0 + wn * 32 + ni * 8 + lc * 2;
            float b0 = 0.f, b1 = 0.f;
            if (bias) {
                if (c0 < N)     b0 = bias[c0];
                if (c0 + 1 < N) b1 = bias[c0 + 1];
            }
            if (r0 < M) {
                if (c0 < N)     C[(long)r0 * ldc + c0]     = acc[mi][ni][0] + b0;
                if (c0 + 1 < N) C[(long)r0 * ldc + c0 + 1] = acc[mi][ni][1] + b1;
            }
            if (r0 + 8 < M) {
                if (c0 < N)     C[(long)(r0 + 8) * ldc + c0]     = acc[mi][ni][2] + b0;
                if (c0 + 1 < N) C[(long)(r0 + 8) * ldc + c0 + 1] = acc[mi][ni][3] + b1;
            }
        }
    }
}

// RMSNorm over full C for q and k segments of one qkv row, in place.
__global__ void rmsnorm_qk(float* __restrict__ qkv,
                           const float* __restrict__ qw, const float* __restrict__ kw)
{
    float* row = qkv + (size_t)blockIdx.x * (3 * C_DIM);
    int tid = threadIdx.x;
    float sq = 0.f, sk = 0.f;
    for (int i = tid * 4; i < C_DIM; i += 256 * 4) {
        float4 q = *reinterpret_cast<const float4*>(row + i);
        float4 k = *reinterpret_cast<const float4*>(row + C_DIM + i);
        sq += q.x * q.x + q.y * q.y + q.z * q.z + q.w * q.w;
        sk += k.x * k.x + k.y * k.y + k.z * k.z + k.w * k.w;
    }
    #pragma unroll
    for (int o = 16; o; o >>= 1) {
        sq += __shfl_xor_sync(0xffffffffu, sq, o);
        sk += __shfl_xor_sync(0xffffffffu, sk, o);
    }
    __shared__ float s1[8], s2[8];
    int lane = tid & 31, warp = tid >> 5;
    if (lane == 0) { s1[warp] = sq; s2[warp] = sk; }
    __syncthreads();
    if (tid == 0) {
        float a = 0.f, b = 0.f;
        #pragma unroll
        for (int w = 0; w < 8; w++) { a += s1[w]; b += s2[w]; }
        s1[0] = rsqrtf(a / C_DIM + 1e-6f);
        s2[0] = rsqrtf(b / C_DIM + 1e-6f);
    }
    __syncthreads();
    float invq = s1[0], invk = s2[0];
    for (int i = tid * 4; i < C_DIM; i += 256 * 4) {
        float4 q = *reinterpret_cast<const float4*>(row + i);
        float4 k = *reinterpret_cast<const float4*>(row + C_DIM + i);
        q.x *= invq * qw[i];     q.y *= invq * qw[i + 1];
        q.z *= invq * qw[i + 2]; q.w *= invq * qw[i + 3];
        k.x *= invk * kw[i];     k.y *= invk * kw[i + 1];
        k.z *= invk * kw[i + 2]; k.w *= invk * kw[i + 3];
        *reinterpret_cast<float4*>(row + i) = q;
        *reinterpret_cast<float4*>(row + C_DIM + i) = k;
    }
}

// Softmax over one score row (1025 valid, stride SD); zeroes the pad columns.
__global__ void softmax_rows(float* __restrict__ S)
{
    float* row = S + ((size_t)blockIdx.y * N_TOK + blockIdx.x) * SD;
    int tid = threadIdx.x;
    int lane = tid & 31, warp = tid >> 5;
    __shared__ float sh[8];

    float v[5];
    float m = -1e30f;
    #pragma unroll
    for (int i = 0; i < 5; i++) {
        int j = tid + i * 256;
        v[i] = (j < N_TOK) ? row[j] : -1e30f;
        m = fmaxf(m, v[i]);
    }
    #pragma unroll
    for (int o = 16; o; o >>= 1) m = fmaxf(m, __shfl_xor_sync(0xffffffffu, m, o));
    if (lane == 0) sh[warp] = m;
    __syncthreads();
    if (tid == 0) {
        float a = sh[0];
        #pragma unroll
        for (int w = 1; w < 8; w++) a = fmaxf(a, sh[w]);
        sh[0] = a;
    }
    __syncthreads();
    m = sh[0];
    __syncthreads();

    float l = 0.f;
    #pragma unroll
    for (int i = 0; i < 5; i++) {
        int j = tid + i * 256;
        v[i] = (j < N_TOK) ? __expf(v[i] - m) : 0.f;
        l += v[i];
    }
    #pragma unroll
    for (int o = 16; o; o >>= 1) l += __shfl_xor_sync(0xffffffffu, l, o);
    if (lane == 0) sh[warp] = l;
    __syncthreads();
    if (tid == 0) {
        float a = 0.f;
        #pragma unroll
        for (int w = 0; w < 8; w++) a += sh[w];
        sh[0] = a;
    }
    __syncthreads();
    float inv = 1.f / sh[0];
    #pragma unroll
    for (int i = 0; i < 5; i++) {
        int j = tid + i * 256;
        if (j < SD) row[j] = v[i] * inv;   // pad cols (1025..1027) get exact 0
    }
}

extern "C" void kernel_launch(void* const* d_in, const int* in_sizes, int n_in,
                              void* d_out, int out_size)
{
    const float* x        = (const float*)d_in[0];
    const float* qkv_w    = (const float*)d_in[1];
    const float* qkv_b    = (const float*)d_in[2];
    const float* q_norm_w = (const float*)d_in[3];
    const float* k_norm_w = (const float*)d_in[4];
    const float* proj_w   = (const float*)d_in[5];
    const float* proj_b   = (const float*)d_in[6];
    float* out = (float*)d_out;

    float *qkvp, *Sp, *attp;
    cudaGetSymbolAddress((void**)&qkvp, g_qkv);
    cudaGetSymbolAddress((void**)&Sp,   g_S);
    cudaGetSymbolAddress((void**)&attp, g_att);

    dim3 blk(256);
    const float qk_scale = 0.088388347648318447f;  // 1/sqrt(128)

    // 1. QKV GEMM: [8200,3200] x [3200,9600] + bias -> g_qkv
    gemm_tf32<false><<<dim3(75, 65, 1), blk>>>(
        x, qkv_w, qkv_b, qkvp, M_ROWS, 3 * C_DIM, C_DIM,
        C_DIM, 3 * C_DIM, 3 * C_DIM,
        0, 0, 0, 0, 0, 0, 1, 1.0f);

    // 2. RMSNorm q,k in place
    rmsnorm_qk<<<M_ROWS, blk>>>(qkvp, q_norm_w, k_norm_w);

    // 3. S = scale * Q K^T, batched over 200 (b,h):  [1025,128] x [1025,128]^T
    gemm_tf32<true><<<dim3(9, 9, 200), blk>>>(
        qkvp, qkvp + C_DIM, nullptr, Sp, N_TOK, N_TOK, D_HEAD,
        3 * C_DIM, 3 * C_DIM, SD,
        (long)N_TOK * 3 * C_DIM, D_HEAD,
        (long)N_TOK * 3 * C_DIM, D_HEAD,
        (long)H_HEADS * N_TOK * SD, (long)N_TOK * SD,
        H_HEADS, qk_scale);

    // 4. Row softmax
    softmax_rows<<<dim3(N_TOK, B_DIM * H_HEADS), blk>>>(Sp);

    // 5. O = P V, batched over 200:  [1025,1025] x [1025,128]
    gemm_tf32<false><<<dim3(1, 9, 200), blk>>>(
        Sp, qkvp + 2 * C_DIM, nullptr, attp, N_TOK, D_HEAD, N_TOK,
        SD, 3 * C_DIM, C_DIM,
        (long)H_HEADS * N_TOK * SD, (long)N_TOK * SD,
        (long)N_TOK * 3 * C_DIM, D_HEAD,
        (long)N_TOK * C_DIM, D_HEAD,
        H_HEADS, 1.0f);

    // 6. Proj GEMM: [8200,3200] x [3200,3200] + bias -> out
    gemm_tf32<false><<<dim3(25, 65, 1), blk>>>(
        attp, proj_w, proj_b, out, M_ROWS, C_DIM, C_DIM,
        C_DIM, C_DIM, C_DIM,
        0, 0, 0, 0, 0, 0, 1, 1.0f);
}

// round 2
// speedup vs baseline: 1.1792x; 1.1792x over previous
#include <cuda_runtime.h>
#include <cuda_bf16.h>
#include <math.h>
#include <stdint.h>

// Problem constants
#define H_HEADS 25
#define B_DIM   8
#define N_TOK   1025
#define C_DIM   3200
#define D_HEAD  128
#define M_ROWS  (B_DIM * N_TOK)   // 8200
#define SD      1028              // padded stride for score rows (16B aligned)

// Scratch (device globals: allocation inside kernel_launch is forbidden)
__device__ float g_qkv[(size_t)M_ROWS * 3 * C_DIM];               // [8200, 9600]
__device__ float g_S[(size_t)B_DIM * H_HEADS * N_TOK * SD];       // [200, 1025, 1028]
__device__ float g_att[(size_t)M_ROWS * C_DIM];                   // [8200, 3200]

__device__ __forceinline__ unsigned u_tf32(float x) {
    float r;
    asm("cvt.rna.tf32.f32 %0, %1;" : "=f"(r) : "f"(x));
    return __float_as_uint(r);
}

__device__ __forceinline__ void cp16(uint32_t dst, const void* src, int bytes) {
    asm volatile("cp.async.cg.shared.global [%0], [%1], 16, %2;\n"
                 :: "r"(dst), "l"(src), "r"(bytes));
}
__device__ __forceinline__ void cp_commit() { asm volatile("cp.async.commit_group;\n" ::); }
__device__ __forceinline__ void cp_wait0()  { asm volatile("cp.async.wait_group 0;\n" ::); }

__device__ __forceinline__ void mma_tf32(float (&d)[4], const unsigned (&a)[4], const unsigned (&b)[2]) {
    asm volatile(
        "mma.sync.aligned.m16n8k8.row.col.f32.tf32.tf32.f32 "
        "{%0,%1,%2,%3}, {%4,%5,%6,%7}, {%8,%9}, {%0,%1,%2,%3};"
        : "+f"(d[0]), "+f"(d[1]), "+f"(d[2]), "+f"(d[3])
        : "r"(a[0]), "r"(a[1]), "r"(a[2]), "r"(a[3]), "r"(b[0]), "r"(b[1]));
}

// Generic batched TF32 GEMM: C = alpha * A (MxK) * B + bias
// TRANS_B=false: B is [K,N] row-major.  TRANS_B=true: B is [N,K] row-major.
// Batch offset for operand X: (z / binner)*Xso + (z % binner)*Xsi.
// Block tile 128x128x32, 256 threads, warp tile 64x32 (2x4 warps), m16n8k8.
// 2-stage cp.async software pipeline; tf32 rounding on register fragments.
template<bool TRANS_B>
__global__ void __launch_bounds__(256, 2)
gemm_tf32(const float* __restrict__ A, const float* __restrict__ B,
          const float* __restrict__ bias, float* __restrict__ C,
          int M, int N, int K,
          long lda, long ldb, long ldc,
          long aso, long asi, long bso, long bsi, long cso, long csi,
          int binner, float alpha)
{
    constexpr int AS_STRIDE = 36;                       // floats; 144B (16B-aligned rows)
    constexpr int BS_STRIDE = TRANS_B ? 36 : 136;       // 144B / 544B, both 16B-aligned
    constexpr int AS_ELE = 128 * AS_STRIDE;             // 4608
    constexpr int BS_ELE = TRANS_B ? 128 * 36 : 32 * 136;  // 4608 / 4352

    extern __shared__ float sm[];
    float* As = sm;                  // [2][AS_ELE]
    float* Bs = sm + 2 * AS_ELE;     // [2][BS_ELE]

    int z = blockIdx.z;
    int zo = z / binner, zi = z - zo * binner;
    A += (long)zo * aso + (long)zi * asi;
    B += (long)zo * bso + (long)zi * bsi;
    C += (long)zo * cso + (long)zi * csi;

    const int bm0 = blockIdx.y * 128;
    const int bn0 = blockIdx.x * 128;
    const int tid = threadIdx.x;
    const int lane = tid & 31, warp = tid >> 5;
    const int wm = warp & 1, wn = warp >> 1;   // 2 x 4 warp grid
    const int lr = lane >> 2, lc = lane & 3;

    float acc[4][4][4];
    #pragma unroll
    for (int mi = 0; mi < 4; mi++)
        #pragma unroll
        for (int ni = 0; ni < 4; ni++)
            #pragma unroll
            for (int r = 0; r < 4; r++)
                acc[mi][ni][r] = 0.f;

    const int T = (K + 31) / 32;

    // ---- tile loader: issue cp.async for k-tile t into stage s ----
    auto load_tiles = [&](int t, int s) {
        int k0 = t * 32;
        uint32_t as_base = __cvta_generic_to_shared(As + s * AS_ELE);
        uint32_t bs_base = __cvta_generic_to_shared(Bs + s * BS_ELE);
        // A tile: 128 x 32, each thread 4 chunks of 16B
        #pragma unroll
        for (int i = 0; i < 4; i++) {
            int f = tid + i * 256;
            int row = f >> 3, kq = (f & 7) * 4;
            int gm = bm0 + row, gk = k0 + kq;
            int bytes = 0;
            const float* src = A;
            if (gm < M) {
                int rem = K - gk;
                if (rem > 0) {
                    bytes = rem >= 4 ? 16 : rem * 4;
                    src = A + (long)gm * lda + gk;
                }
            }
            cp16(as_base + (uint32_t)(row * AS_STRIDE + kq) * 4u, src, bytes);
        }
        if (!TRANS_B) {
            // B tile [k][n]: rows of global B are k; contiguous along n
            #pragma unroll
            for (int i = 0; i < 4; i++) {
                int f = tid + i * 256;
                int kr = f >> 5, nq = (f & 31) * 4;
                int gk = k0 + kr, gn = bn0 + nq;
                int bytes = 0;
                const float* src = B;
                if (gk < K && gn < N) {
                    bytes = 16;
                    src = B + (long)gk * ldb + gn;
                }
                cp16(bs_base + (uint32_t)(kr * 136 + nq) * 4u, src, bytes);
            }
        } else {
            // B tile [n][k]: rows of global B are n; contiguous along k
            #pragma unroll
            for (int i = 0; i < 4; i++) {
                int f = tid + i * 256;
                int nrow = f >> 3, kq = (f & 7) * 4;
                int gn = bn0 + nrow, gk = k0 + kq;
                int bytes = 0;
                const float* src = B;
                if (gn < N) {
                    int rem = K - gk;
                    if (rem > 0) {
                        bytes = rem >= 4 ? 16 : rem * 4;
                        src = B + (long)gn * ldb + gk;
                    }
                }
                cp16(bs_base + (uint32_t)(nrow * 36 + kq) * 4u, src, bytes);
            }
        }
    };

    // ---- prologue ----
    load_tiles(0, 0);
    cp_commit();

    int buf = 0;
    for (int t = 0; t < T; t++) {
        cp_wait0();
        __syncthreads();           // stage `buf` ready; all compute on old buf done
        if (t + 1 < T) {
            load_tiles(t + 1, buf ^ 1);
            cp_commit();
        }
        // ---- compute stage `buf`: 4 k8 steps, 16 mma each ----
        const float* Asb = As + buf * AS_ELE;
        const float* Bsb = Bs + buf * BS_ELE;
        #pragma unroll
        for (int ks = 0; ks < 4; ks++) {
            unsigned af[4][4], bf[4][2];
            #pragma unroll
            for (int mi = 0; mi < 4; mi++) {
                const float* p = &Asb[(wm * 64 + mi * 16 + lr) * AS_STRIDE + ks * 8 + lc];
                af[mi][0] = u_tf32(p[0]);
                af[mi][1] = u_tf32(p[8 * AS_STRIDE]);
                af[mi][2] = u_tf32(p[4]);
                af[mi][3] = u_tf32(p[8 * AS_STRIDE + 4]);
            }
            #pragma unroll
            for (int ni = 0; ni < 4; ni++) {
                if (TRANS_B) {
                    const float* p = &Bsb[(wn * 32 + ni * 8 + lr) * 36 + ks * 8 + lc];
                    bf[ni][0] = u_tf32(p[0]);
                    bf[ni][1] = u_tf32(p[4]);
                } else {
                    const float* p = &Bsb[(ks * 8 + lc) * 136 + wn * 32 + ni * 8 + lr];
                    bf[ni][0] = u_tf32(p[0]);
                    bf[ni][1] = u_tf32(p[4 * 136]);
                }
            }
            #pragma unroll
            for (int mi = 0; mi < 4; mi++)
                #pragma unroll
                for (int ni = 0; ni < 4; ni++)
                    mma_tf32(acc[mi][ni], af[mi], bf[ni]);
        }
        buf ^= 1;
    }

    // ---- Epilogue: out = alpha*acc + bias ----
    #pragma unroll
    for (int mi = 0; mi < 4; mi++) {
        #pragma unroll
        for (int ni = 0; ni < 4; ni++) {
            int r0 = bm0 + wm * 64 + mi * 16 + lr;
            int c0 = bn0 + wn * 32 + ni * 8 + lc * 2;
            float b0 = 0.f, b1 = 0.f;
            if (bias) {
                if (c0 < N)     b0 = bias[c0];
                if (c0 + 1 < N) b1 = bias[c0 + 1];
            }
            if (r0 < M) {
                if (c0 < N)     C[(long)r0 * ldc + c0]     = alpha * acc[mi][ni][0] + b0;
                if (c0 + 1 < N) C[(long)r0 * ldc + c0 + 1] = alpha * acc[mi][ni][1] + b1;
            }
            if (r0 + 8 < M) {
                if (c0 < N)     C[(long)(r0 + 8) * ldc + c0]     = alpha * acc[mi][ni][2] + b0;
                if (c0 + 1 < N) C[(long)(r0 + 8) * ldc + c0 + 1] = alpha * acc[mi][ni][3] + b1;
            }
        }
    }
}

// RMSNorm over full C for q and k segments of one qkv row, in place.
__global__ void rmsnorm_qk(float* __restrict__ qkv,
                           const float* __restrict__ qw, const float* __restrict__ kw)
{
    float* row = qkv + (size_t)blockIdx.x * (3 * C_DIM);
    int tid = threadIdx.x;
    float sq = 0.f, sk = 0.f;
    for (int i = tid * 4; i < C_DIM; i += 256 * 4) {
        float4 q = *reinterpret_cast<const float4*>(row + i);
        float4 k = *reinterpret_cast<const float4*>(row + C_DIM + i);
        sq += q.x * q.x + q.y * q.y + q.z * q.z + q.w * q.w;
        sk += k.x * k.x + k.y * k.y + k.z * k.z + k.w * k.w;
    }
    #pragma unroll
    for (int o = 16; o; o >>= 1) {
        sq += __shfl_xor_sync(0xffffffffu, sq, o);
        sk += __shfl_xor_sync(0xffffffffu, sk, o);
    }
    __shared__ float s1[8], s2[8];
    int lane = tid & 31, warp = tid >> 5;
    if (lane == 0) { s1[warp] = sq; s2[warp] = sk; }
    __syncthreads();
    if (tid == 0) {
        float a = 0.f, b = 0.f;
        #pragma unroll
        for (int w = 0; w < 8; w++) { a += s1[w]; b += s2[w]; }
        s1[0] = rsqrtf(a / C_DIM + 1e-6f);
        s2[0] = rsqrtf(b / C_DIM + 1e-6f);
    }
    __syncthreads();
    float invq = s1[0], invk = s2[0];
    for (int i = tid * 4; i < C_DIM; i += 256 * 4) {
        float4 q = *reinterpret_cast<const float4*>(row + i);
        float4 k = *reinterpret_cast<const float4*>(row + C_DIM + i);
        q.x *= invq * qw[i];     q.y *= invq * qw[i + 1];
        q.z *= invq * qw[i + 2]; q.w *= invq * qw[i + 3];
        k.x *= invk * kw[i];     k.y *= invk * kw[i + 1];
        k.z *= invk * kw[i + 2]; k.w *= invk * kw[i + 3];
        *reinterpret_cast<float4*>(row + i) = q;
        *reinterpret_cast<float4*>(row + C_DIM + i) = k;
    }
}

// Softmax over one score row (1025 valid, stride SD); zeroes the pad columns.
__global__ void softmax_rows(float* __restrict__ S)
{
    float* row = S + ((size_t)blockIdx.y * N_TOK + blockIdx.x) * SD;
    int tid = threadIdx.x;
    int lane = tid & 31, warp = tid >> 5;
    __shared__ float sh[8];

    float v[5];
    float m = -1e30f;
    #pragma unroll
    for (int i = 0; i < 5; i++) {
        int j = tid + i * 256;
        v[i] = (j < N_TOK) ? row[j] : -1e30f;
        m = fmaxf(m, v[i]);
    }
    #pragma unroll
    for (int o = 16; o; o >>= 1) m = fmaxf(m, __shfl_xor_sync(0xffffffffu, m, o));
    if (lane == 0) sh[warp] = m;
    __syncthreads();
    if (tid == 0) {
        float a = sh[0];
        #pragma unroll
        for (int w = 1; w < 8; w++) a = fmaxf(a, sh[w]);
        sh[0] = a;
    }
    __syncthreads();
    m = sh[0];
    __syncthreads();

    float l = 0.f;
    #pragma unroll
    for (int i = 0; i < 5; i++) {
        int j = tid + i * 256;
        v[i] = (j < N_TOK) ? __expf(v[i] - m) : 0.f;
        l += v[i];
    }
    #pragma unroll
    for (int o = 16; o; o >>= 1) l += __shfl_xor_sync(0xffffffffu, l, o);
    if (lane == 0) sh[warp] = l;
    __syncthreads();
    if (tid == 0) {
        float a = 0.f;
        #pragma unroll
        for (int w = 0; w < 8; w++) a += sh[w];
        sh[0] = a;
    }
    __syncthreads();
    float inv = 1.f / sh[0];
    #pragma unroll
    for (int i = 0; i < 5; i++) {
        int j = tid + i * 256;
        if (j < SD) row[j] = v[i] * inv;   // pad cols (1025..1027) get exact 0
    }
}

extern "C" void kernel_launch(void* const* d_in, const int* in_sizes, int n_in,
                              void* d_out, int out_size)
{
    const float* x        = (const float*)d_in[0];
    const float* qkv_w    = (const float*)d_in[1];
    const float* qkv_b    = (const float*)d_in[2];
    const float* q_norm_w = (const float*)d_in[3];
    const float* k_norm_w = (const float*)d_in[4];
    const float* proj_w   = (const float*)d_in[5];
    const float* proj_b   = (const float*)d_in[6];
    float* out = (float*)d_out;

    float *qkvp, *Sp, *attp;
    cudaGetSymbolAddress((void**)&qkvp, g_qkv);
    cudaGetSymbolAddress((void**)&Sp,   g_S);
    cudaGetSymbolAddress((void**)&attp, g_att);

    // Dynamic smem: 2 stages of (A tile + B tile)
    const int smem_nt = 2 * (128 * 36 + 32 * 136) * (int)sizeof(float);   // 71680
    const int smem_t  = 2 * (128 * 36 + 128 * 36) * (int)sizeof(float);   // 73728
    cudaFuncSetAttribute(gemm_tf32<false>, cudaFuncAttributeMaxDynamicSharedMemorySize, smem_nt);
    cudaFuncSetAttribute(gemm_tf32<true>,  cudaFuncAttributeMaxDynamicSharedMemorySize, smem_t);

    dim3 blk(256);
    const float qk_scale = 0.088388347648318447f;  // 1/sqrt(128)

    // 1. QKV GEMM: [8200,3200] x [3200,9600] + bias -> g_qkv
    gemm_tf32<false><<<dim3(75, 65, 1), blk, smem_nt>>>(
        x, qkv_w, qkv_b, qkvp, M_ROWS, 3 * C_DIM, C_DIM,
        C_DIM, 3 * C_DIM, 3 * C_DIM,
        0, 0, 0, 0, 0, 0, 1, 1.0f);

    // 2. RMSNorm q,k in place
    rmsnorm_qk<<<M_ROWS, blk>>>(qkvp, q_norm_w, k_norm_w);

    // 3. S = scale * Q K^T, batched over 200 (b,h):  [1025,128] x [1025,128]^T
    gemm_tf32<true><<<dim3(9, 9, 200), blk, smem_t>>>(
        qkvp, qkvp + C_DIM, nullptr, Sp, N_TOK, N_TOK, D_HEAD,
        3 * C_DIM, 3 * C_DIM, SD,
        (long)N_TOK * 3 * C_DIM, D_HEAD,
        (long)N_TOK * 3 * C_DIM, D_HEAD,
        (long)H_HEADS * N_TOK * SD, (long)N_TOK * SD,
        H_HEADS, qk_scale);

    // 4. Row softmax
    softmax_rows<<<dim3(N_TOK, B_DIM * H_HEADS), blk>>>(Sp);

    // 5. O = P V, batched over 200:  [1025,1025] x [1025,128]
    gemm_tf32<false><<<dim3(1, 9, 200), blk, smem_nt>>>(
        Sp, qkvp + 2 * C_DIM, nullptr, attp, N_TOK, D_HEAD, N_TOK,
        SD, 3 * C_DIM, C_DIM,
        (long)H_HEADS * N_TOK * SD, (long)N_TOK * SD,
        (long)N_TOK * 3 * C_DIM, D_HEAD,
        (long)N_TOK * C_DIM, D_HEAD,
        H_HEADS, 1.0f);

    // 6. Proj GEMM: [8200,3200] x [3200,3200] + bias -> out
    gemm_tf32<false><<<dim3(25, 65, 1), blk, smem_nt>>>(
        attp, proj_w, proj_b, out, M_ROWS, C_DIM, C_DIM,
        C_DIM, C_DIM, C_DIM,
        0, 0, 0, 0, 0, 0, 1, 1.0f);
}

// round 4
// speedup vs baseline: 1.3070x; 1.1083x over previous
#include <cuda_runtime.h>
#include <cuda_bf16.h>
#include <math.h>
#include <stdint.h>

// Problem constants
#define H_HEADS 25
#define B_DIM   8
#define N_TOK   1025
#define C_DIM   3200
#define D_HEAD  128
#define M_ROWS  (B_DIM * N_TOK)   // 8200
#define SD      1028              // padded stride for score rows (16B aligned)

// Scratch (device globals: allocation inside kernel_launch is forbidden)
__device__ float g_qkv[(size_t)M_ROWS * 3 * C_DIM];               // [8200, 9600]
__device__ float g_S[(size_t)B_DIM * H_HEADS * N_TOK * SD];       // [200, 1025, 1028]
__device__ float g_att[(size_t)M_ROWS * C_DIM];                   // [8200, 3200]
__device__ float g_x[(size_t)M_ROWS * C_DIM];                     // rounded copy of x
__device__ float g_wqkv[(size_t)C_DIM * 3 * C_DIM];               // rounded qkv_w
__device__ float g_wproj[(size_t)C_DIM * C_DIM];                  // rounded proj_w

__device__ __forceinline__ float f_tf32(float x) {
    float r;
    asm("cvt.rna.tf32.f32 %0, %1;" : "=f"(r) : "f"(x));
    return r;
}

__device__ __forceinline__ void cp16(uint32_t dst, const void* src, int bytes) {
    asm volatile("cp.async.cg.shared.global [%0], [%1], 16, %2;\n"
                 :: "r"(dst), "l"(src), "r"(bytes));
}
__device__ __forceinline__ void cp_commit() { asm volatile("cp.async.commit_group;\n" ::); }
template<int NN>
__device__ __forceinline__ void cp_wait() { asm volatile("cp.async.wait_group %0;\n" :: "n"(NN)); }

__device__ __forceinline__ uint32_t smem_u32(const void* p) {
    return (uint32_t)__cvta_generic_to_shared(p);
}

__device__ __forceinline__ void mma_tf32(float (&d)[4], const unsigned (&a)[4], const unsigned (&b)[2]) {
    asm volatile(
        "mma.sync.aligned.m16n8k8.row.col.f32.tf32.tf32.f32 "
        "{%0,%1,%2,%3}, {%4,%5,%6,%7}, {%8,%9}, {%0,%1,%2,%3};"
        : "+f"(d[0]), "+f"(d[1]), "+f"(d[2]), "+f"(d[3])
        : "r"(a[0]), "r"(a[1]), "r"(a[2]), "r"(a[3]), "r"(b[0]), "r"(b[1]));
}

// =====================================================================
// Batched TF32 GEMM, operands PRE-ROUNDED to tf32 in gmem (no in-loop cvt).
// C = alpha * A (MxK) * B + bias
// TRANS_B=false: B is [K,N] row-major.  TRANS_B=true: B is [N,K] row-major.
// Block tile 128 x BN (BN=128 or 256), 256 threads, warp tile 64 x (BN/4).
// 3-stage cp.async pipeline. Optional m-grouped rasterization (TM>0).
// =====================================================================
template<int BN, bool TRANS_B>
__global__ void __launch_bounds__(256, (BN == 256) ? 1 : 2)
gemm_tf32(const float* __restrict__ A, const float* __restrict__ B,
          const float* __restrict__ bias, float* __restrict__ C,
          int M, int N, int K,
          long lda, long ldb, long ldc,
          long aso, long asi, long bso, long bsi, long cso, long csi,
          int binner, float alpha, int round_out, int TM, int TN)
{
    constexpr int NFR = BN / 32;                    // n-fragments per warp (4 or 8)
    constexpr int AS_STRIDE = 36;
    constexpr int BS_STRIDE = TRANS_B ? 36 : (BN + 8);
    constexpr int AS_ELE = 128 * AS_STRIDE;
    constexpr int BS_ELE = TRANS_B ? BN * 36 : 32 * (BN + 8);
    constexpr int STAGES = 3;

    extern __shared__ float sm[];
    float* As = sm;                        // [STAGES][AS_ELE]
    float* Bs = sm + STAGES * AS_ELE;      // [STAGES][BS_ELE]

    int z = blockIdx.z;
    int zo = z / binner, zi = z - zo * binner;
    A += (long)zo * aso + (long)zi * asi;
    B += (long)zo * bso + (long)zi * bsi;
    C += (long)zo * cso + (long)zi * csi;

    // tile mapping
    int tm, tn;
    if (TM > 0) {
        const int GM = 16;
        int per = GM * TN;
        int g = blockIdx.x / per, r = blockIdx.x - g * per;
        int rows = TM - g * GM; if (rows > GM) rows = GM;
        tm = g * GM + r % rows;
        tn = r / rows;
    } else {
        tm = blockIdx.y; tn = blockIdx.x;
    }
    const int bm0 = tm * 128;
    const int bn0 = tn * BN;

    const int tid = threadIdx.x;
    const int lane = tid & 31, warp = tid >> 5;
    const int wm = warp & 1, wn = warp >> 1;   // 2 x 4 warp grid
    const int lr = lane >> 2, lc = lane & 3;

    float acc[4][NFR][4];
    #pragma unroll
    for (int mi = 0; mi < 4; mi++)
        #pragma unroll
        for (int ni = 0; ni < NFR; ni++)
            #pragma unroll
            for (int r = 0; r < 4; r++)
                acc[mi][ni][r] = 0.f;

    const int T = (K + 31) / 32;

    auto load_tiles = [&](int t, int s) {
        int k0 = t * 32;
        uint32_t as_base = smem_u32(As + s * AS_ELE);
        uint32_t bs_base = smem_u32(Bs + s * BS_ELE);
        // A tile: 128 x 32
        #pragma unroll
        for (int i = 0; i < 4; i++) {
            int f = tid + i * 256;
            int row = f >> 3, kq = (f & 7) * 4;
            int gm = bm0 + row, gk = k0 + kq;
            int bytes = 0;
            const float* src = A;
            if (gm < M) {
                int rem = K - gk;
                if (rem > 0) { bytes = rem >= 4 ? 16 : rem * 4; src = A + (long)gm * lda + gk; }
            }
            cp16(as_base + (uint32_t)(row * AS_STRIDE + kq) * 4u, src, bytes);
        }
        if (!TRANS_B) {
            // B tile [k][n]: 32 x BN
            #pragma unroll
            for (int i = 0; i < BN / 32; i++) {
                int f = tid + i * 256;
                int kr = f / (BN / 4), nq = (f % (BN / 4)) * 4;
                int gk = k0 + kr, gn = bn0 + nq;
                int bytes = 0;
                const float* src = B;
                if (gk < K && gn < N) { bytes = 16; src = B + (long)gk * ldb + gn; }
                cp16(bs_base + (uint32_t)(kr * BS_STRIDE + nq) * 4u, src, bytes);
            }
        } else {
            // B tile [n][k]: BN x 32
            #pragma unroll
            for (int i = 0; i < BN / 32; i++) {
                int f = tid + i * 256;
                int nrow = f >> 3, kq = (f & 7) * 4;
                int gn = bn0 + nrow, gk = k0 + kq;
                int bytes = 0;
                const float* src = B;
                if (gn < N) {
                    int rem = K - gk;
                    if (rem > 0) { bytes = rem >= 4 ? 16 : rem * 4; src = B + (long)gn * ldb + gk; }
                }
                cp16(bs_base + (uint32_t)(nrow * 36 + kq) * 4u, src, bytes);
            }
        }
    };

    // prologue: 2 tiles in flight
    load_tiles(0, 0);
    cp_commit();
    if (T > 1) { load_tiles(1, 1); }
    cp_commit();      // commit even if empty to keep group accounting simple

    for (int t = 0; t < T; t++) {
        if (t + 1 < T) cp_wait<1>(); else cp_wait<0>();
        __syncthreads();
        if (t + 2 < T) { load_tiles(t + 2, (t + 2) % STAGES); }
        cp_commit();
        const float* Asb = As + (t % STAGES) * AS_ELE;
        const float* Bsb = Bs + (t % STAGES) * BS_ELE;
        #pragma unroll
        for (int ks = 0; ks < 4; ks++) {
            unsigned af[4][4], bf[NFR][2];
            #pragma unroll
            for (int mi = 0; mi < 4; mi++) {
                const float* p = &Asb[(wm * 64 + mi * 16 + lr) * AS_STRIDE + ks * 8 + lc];
                af[mi][0] = __float_as_uint(p[0]);
                af[mi][1] = __float_as_uint(p[8 * AS_STRIDE]);
                af[mi][2] = __float_as_uint(p[4]);
                af[mi][3] = __float_as_uint(p[8 * AS_STRIDE + 4]);
            }
            #pragma unroll
            for (int ni = 0; ni < NFR; ni++) {
                if (TRANS_B) {
                    const float* p = &Bsb[(wn * (BN / 4) + ni * 8 + lr) * 36 + ks * 8 + lc];
                    bf[ni][0] = __float_as_uint(p[0]);
                    bf[ni][1] = __float_as_uint(p[4]);
                } else {
                    const float* p = &Bsb[(ks * 8 + lc) * BS_STRIDE + wn * (BN / 4) + ni * 8 + lr];
                    bf[ni][0] = __float_as_uint(p[0]);
                    bf[ni][1] = __float_as_uint(p[4 * BS_STRIDE]);
                }
            }
            #pragma unroll
            for (int mi = 0; mi < 4; mi++)
                #pragma unroll
                for (int ni = 0; ni < NFR; ni++)
                    mma_tf32(acc[mi][ni], af[mi], bf[ni]);
        }
        __syncthreads();
    }

    // epilogue
    #pragma unroll
    for (int mi = 0; mi < 4; mi++) {
        #pragma unroll
        for (int ni = 0; ni < NFR; ni++) {
            int r0 = bm0 + wm * 64 + mi * 16 + lr;
            int c0 = bn0 + wn * (BN / 4) + ni * 8 + lc * 2;
            float b0 = 0.f, b1 = 0.f;
            if (bias) {
                if (c0 < N)     b0 = bias[c0];
                if (c0 + 1 < N) b1 = bias[c0 + 1];
            }
            #pragma unroll
            for (int rr = 0; rr < 2; rr++) {
                int rw = r0 + rr * 8;
                if (rw < M) {
                    float v0 = alpha * acc[mi][ni][rr * 2]     + b0;
                    float v1 = alpha * acc[mi][ni][rr * 2 + 1] + b1;
                    if (round_out) { v0 = f_tf32(v0); v1 = f_tf32(v1); }
                    if (c0 < N)     C[(long)rw * ldc + c0]     = v0;
                    if (c0 + 1 < N) C[(long)rw * ldc + c0 + 1] = v1;
                }
            }
        }
    }
}

// ===================== pre/post-processing kernels =====================

__global__ void round_copy(const float* __restrict__ in, float* __restrict__ out, long n4)
{
    long i = (long)blockIdx.x * blockDim.x + threadIdx.x;
    long stride = (long)gridDim.x * blockDim.x;
    for (; i < n4; i += stride) {
        float4 v = reinterpret_cast<const float4*>(in)[i];
        v.x = f_tf32(v.x); v.y = f_tf32(v.y); v.z = f_tf32(v.z); v.w = f_tf32(v.w);
        reinterpret_cast<float4*>(out)[i] = v;
    }
}

// RMSNorm over full C for q and k segments of one qkv row, in place (tf32-rounded out).
__global__ void rmsnorm_qk(float* __restrict__ qkv,
                           const float* __restrict__ qw, const float* __restrict__ kw)
{
    float* row = qkv + (size_t)blockIdx.x * (3 * C_DIM);
    int tid = threadIdx.x;
    float sq = 0.f, sk = 0.f;
    for (int i = tid * 4; i < C_DIM; i += 256 * 4) {
        float4 q = *reinterpret_cast<const float4*>(row + i);
        float4 k = *reinterpret_cast<const float4*>(row + C_DIM + i);
        sq += q.x * q.x + q.y * q.y + q.z * q.z + q.w * q.w;
        sk += k.x * k.x + k.y * k.y + k.z * k.z + k.w * k.w;
    }
    #pragma unroll
    for (int o = 16; o; o >>= 1) {
        sq += __shfl_xor_sync(0xffffffffu, sq, o);
        sk += __shfl_xor_sync(0xffffffffu, sk, o);
    }
    __shared__ float s1[8], s2[8];
    int lane = tid & 31, warp = tid >> 5;
    if (lane == 0) { s1[warp] = sq; s2[warp] = sk; }
    __syncthreads();
    if (tid == 0) {
        float a = 0.f, b = 0.f;
        #pragma unroll
        for (int w = 0; w < 8; w++) { a += s1[w]; b += s2[w]; }
        s1[0] = rsqrtf(a / C_DIM + 1e-6f);
        s2[0] = rsqrtf(b / C_DIM + 1e-6f);
    }
    __syncthreads();
    float invq = s1[0], invk = s2[0];
    for (int i = tid * 4; i < C_DIM; i += 256 * 4) {
        float4 q = *reinterpret_cast<const float4*>(row + i);
        float4 k = *reinterpret_cast<const float4*>(row + C_DIM + i);
        q.x = f_tf32(q.x * invq * qw[i]);     q.y = f_tf32(q.y * invq * qw[i + 1]);
        q.z = f_tf32(q.z * invq * qw[i + 2]); q.w = f_tf32(q.w * invq * qw[i + 3]);
        k.x = f_tf32(k.x * invk * kw[i]);     k.y = f_tf32(k.y * invk * kw[i + 1]);
        k.z = f_tf32(k.z * invk * kw[i + 2]); k.w = f_tf32(k.w * invk * kw[i + 3]);
        *reinterpret_cast<float4*>(row + i) = q;
        *reinterpret_cast<float4*>(row + C_DIM + i) = k;
    }
}

// Softmax over one score row (1025 valid, stride SD); writes tf32-rounded; zeroes pad.
__global__ void softmax_rows(float* __restrict__ S)
{
    float* row = S + ((size_t)blockIdx.y * N_TOK + blockIdx.x) * SD;
    int tid = threadIdx.x;
    int lane = tid & 31, warp = tid >> 5;
    __shared__ float sh[8];

    float v[5];
    float m = -1e30f;
    #pragma unroll
    for (int i = 0; i < 5; i++) {
        int j = tid + i * 256;
        v[i] = (j < N_TOK) ? row[j] : -1e30f;
        m = fmaxf(m, v[i]);
    }
    #pragma unroll
    for (int o = 16; o; o >>= 1) m = fmaxf(m, __shfl_xor_sync(0xffffffffu, m, o));
    if (lane == 0) sh[warp] = m;
    __syncthreads();
    if (tid == 0) {
        float a = sh[0];
        #pragma unroll
        for (int w = 1; w < 8; w++) a = fmaxf(a, sh[w]);
        sh[0] = a;
    }
    __syncthreads();
    m = sh[0];
    __syncthreads();

    float l = 0.f;
    #pragma unroll
    for (int i = 0; i < 5; i++) {
        int j = tid + i * 256;
        v[i] = (j < N_TOK) ? __expf(v[i] - m) : 0.f;
        l += v[i];
    }
    #pragma unroll
    for (int o = 16; o; o >>= 1) l += __shfl_xor_sync(0xffffffffu, l, o);
    if (lane == 0) sh[warp] = l;
    __syncthreads();
    if (tid == 0) {
        float a = 0.f;
        #pragma unroll
        for (int w = 0; w < 8; w++) a += sh[w];
        sh[0] = a;
    }
    __syncthreads();
    float inv = 1.f / sh[0];
    #pragma unroll
    for (int i = 0; i < 5; i++) {
        int j = tid + i * 256;
        if (j < SD) row[j] = f_tf32(v[i] * inv);   // pad cols stay exact 0
    }
}

extern "C" void kernel_launch(void* const* d_in, const int* in_sizes, int n_in,
                              void* d_out, int out_size)
{
    const float* x        = (const float*)d_in[0];
    const float* qkv_w    = (const float*)d_in[1];
    const float* qkv_b    = (const float*)d_in[2];
    const float* q_norm_w = (const float*)d_in[3];
    const float* k_norm_w = (const float*)d_in[4];
    const float* proj_w   = (const float*)d_in[5];
    const float* proj_b   = (const float*)d_in[6];
    float* out = (float*)d_out;

    float *qkvp, *Sp, *attp, *xp, *wqkvp, *wprojp;
    cudaGetSymbolAddress((void**)&qkvp,  g_qkv);
    cudaGetSymbolAddress((void**)&Sp,    g_S);
    cudaGetSymbolAddress((void**)&attp,  g_att);
    cudaGetSymbolAddress((void**)&xp,    g_x);
    cudaGetSymbolAddress((void**)&wqkvp, g_wqkv);
    cudaGetSymbolAddress((void**)&wprojp,g_wproj);

    // smem sizes per instantiation (3 stages)
    const int smem_big = 3 * (128 * 36 + 32 * 264) * (int)sizeof(float);   // 156672
    const int smem_qk  = 3 * (128 * 36 + 128 * 36) * (int)sizeof(float);   // 110592
    const int smem_pv  = 3 * (128 * 36 + 32 * 136) * (int)sizeof(float);   // 107520
    cudaFuncSetAttribute(gemm_tf32<256, false>, cudaFuncAttributeMaxDynamicSharedMemorySize, smem_big);
    cudaFuncSetAttribute(gemm_tf32<128, true>,  cudaFuncAttributeMaxDynamicSharedMemorySize, smem_qk);
    cudaFuncSetAttribute(gemm_tf32<128, false>, cudaFuncAttributeMaxDynamicSharedMemorySize, smem_pv);

    dim3 blk(256);
    const float qk_scale = 0.088388347648318447f;  // 1/sqrt(128)

    // 0. Pre-round operands once
    round_copy<<<2048, 256>>>(x, xp, (long)M_ROWS * C_DIM / 4);
    round_copy<<<2048, 256>>>(qkv_w, wqkvp, (long)C_DIM * 3 * C_DIM / 4);
    round_copy<<<2048, 256>>>(proj_w, wprojp, (long)C_DIM * C_DIM / 4);

    // 1. QKV GEMM: [8200,3200] x [3200,9600] + bias -> g_qkv (rounded out)
    {
        int TM = (M_ROWS + 127) / 128;          // 65
        int TN = (3 * C_DIM + 255) / 256;       // 38
        gemm_tf32<256, false><<<dim3(TM * TN, 1, 1), blk, smem_big>>>(
            xp, wqkvp, qkv_b, qkvp, M_ROWS, 3 * C_DIM, C_DIM,
            C_DIM, 3 * C_DIM, 3 * C_DIM,
            0, 0, 0, 0, 0, 0, 1, 1.0f, 1, TM, TN);
    }

    // 2. RMSNorm q,k in place (rounded out)
    rmsnorm_qk<<<M_ROWS, blk>>>(qkvp, q_norm_w, k_norm_w);

    // 3. S = scale * Q K^T, batched over 200 (b,h)
    gemm_tf32<128, true><<<dim3(9, 9, 200), blk, smem_qk>>>(
        qkvp, qkvp + C_DIM, nullptr, Sp, N_TOK, N_TOK, D_HEAD,
        3 * C_DIM, 3 * C_DIM, SD,
        (long)N_TOK * 3 * C_DIM, D_HEAD,
        (long)N_TOK * 3 * C_DIM, D_HEAD,
        (long)H_HEADS * N_TOK * SD, (long)N_TOK * SD,
        H_HEADS, qk_scale, 0, 0, 0);

    // 4. Row softmax (rounded out)
    softmax_rows<<<dim3(N_TOK, B_DIM * H_HEADS), blk>>>(Sp);

    // 5. O = P V, batched over 200 (rounded out for proj)
    gemm_tf32<128, false><<<dim3(1, 9, 200), blk, smem_pv>>>(
        Sp, qkvp + 2 * C_DIM, nullptr, attp, N_TOK, D_HEAD, N_TOK,
        SD, 3 * C_DIM, C_DIM,
        (long)H_HEADS * N_TOK * SD, (long)N_TOK * SD,
        (long)N_TOK * 3 * C_DIM, D_HEAD,
        (long)N_TOK * C_DIM, D_HEAD,
        H_HEADS, 1.0f, 1, 0, 0);

    // 6. Proj GEMM: [8200,3200] x [3200,3200] + bias -> out
    {
        int TM = (M_ROWS + 127) / 128;          // 65
        int TN = (C_DIM + 255) / 256;           // 13
        gemm_tf32<256, false><<<dim3(TM * TN, 1, 1), blk, smem_big>>>(
            attp, wprojp, proj_b, out, M_ROWS, C_DIM, C_DIM,
            C_DIM, C_DIM, C_DIM,
            0, 0, 0, 0, 0, 0, 1, 1.0f, 0, TM, TN);
    }
}

// round 5
// speedup vs baseline: 1.3109x; 1.0030x over previous
#include <cuda_runtime.h>
#include <cuda_bf16.h>
#include <math.h>
#include <stdint.h>

// Problem constants
#define H_HEADS 25
#define B_DIM   8
#define N_TOK   1025
#define C_DIM   3200
#define D_HEAD  128
#define M_ROWS  (B_DIM * N_TOK)   // 8200

// Scratch (device globals: allocation inside kernel_launch is forbidden)
__device__ float g_qkv[(size_t)M_ROWS * 3 * C_DIM];               // [8200, 9600]
__device__ float g_att[(size_t)M_ROWS * C_DIM];                   // [8200, 3200]
__device__ float g_x[(size_t)M_ROWS * C_DIM];                     // rounded copy of x
__device__ float g_wqkv[(size_t)C_DIM * 3 * C_DIM];               // rounded qkv_w
__device__ float g_wproj[(size_t)C_DIM * C_DIM];                  // rounded proj_w

__device__ __forceinline__ float f_tf32(float x) {
    float r;
    asm("cvt.rna.tf32.f32 %0, %1;" : "=f"(r) : "f"(x));
    return r;
}

__device__ __forceinline__ void cp16(uint32_t dst, const void* src, int bytes) {
    asm volatile("cp.async.cg.shared.global [%0], [%1], 16, %2;\n"
                 :: "r"(dst), "l"(src), "r"(bytes));
}
__device__ __forceinline__ void cp_commit() { asm volatile("cp.async.commit_group;\n" ::); }
template<int NN>
__device__ __forceinline__ void cp_wait() { asm volatile("cp.async.wait_group %0;\n" :: "n"(NN)); }

__device__ __forceinline__ uint32_t smem_u32(const void* p) {
    return (uint32_t)__cvta_generic_to_shared(p);
}

__device__ __forceinline__ void mma_tf32(float (&d)[4], const unsigned (&a)[4], const unsigned (&b)[2]) {
    asm volatile(
        "mma.sync.aligned.m16n8k8.row.col.f32.tf32.tf32.f32 "
        "{%0,%1,%2,%3}, {%4,%5,%6,%7}, {%8,%9}, {%0,%1,%2,%3};"
        : "+f"(d[0]), "+f"(d[1]), "+f"(d[2]), "+f"(d[3])
        : "r"(a[0]), "r"(a[1]), "r"(a[2]), "r"(a[3]), "r"(b[0]), "r"(b[1]));
}

// =====================================================================
// Batched TF32 GEMM, operands PRE-ROUNDED to tf32 in gmem.
// (kept from R4 — used for QKV and Proj GEMMs only)
// =====================================================================
template<int BN, bool TRANS_B>
__global__ void __launch_bounds__(256, (BN == 256) ? 1 : 2)
gemm_tf32(const float* __restrict__ A, const float* __restrict__ B,
          const float* __restrict__ bias, float* __restrict__ C,
          int M, int N, int K,
          long lda, long ldb, long ldc,
          float alpha, int round_out, int TM, int TN)
{
    constexpr int NFR = BN / 32;
    constexpr int AS_STRIDE = 36;
    constexpr int BS_STRIDE = TRANS_B ? 36 : (BN + 8);
    constexpr int AS_ELE = 128 * AS_STRIDE;
    constexpr int BS_ELE = TRANS_B ? BN * 36 : 32 * (BN + 8);
    constexpr int STAGES = 3;

    extern __shared__ float sm[];
    float* As = sm;
    float* Bs = sm + STAGES * AS_ELE;

    // m-grouped rasterization
    int tm, tn;
    {
        const int GM = 16;
        int per = GM * TN;
        int g = blockIdx.x / per, r = blockIdx.x - g * per;
        int rows = TM - g * GM; if (rows > GM) rows = GM;
        tm = g * GM + r % rows;
        tn = r / rows;
    }
    const int bm0 = tm * 128;
    const int bn0 = tn * BN;

    const int tid = threadIdx.x;
    const int lane = tid & 31, warp = tid >> 5;
    const int wm = warp & 1, wn = warp >> 1;
    const int lr = lane >> 2, lc = lane & 3;

    float acc[4][NFR][4];
    #pragma unroll
    for (int mi = 0; mi < 4; mi++)
        #pragma unroll
        for (int ni = 0; ni < NFR; ni++)
            #pragma unroll
            for (int r = 0; r < 4; r++)
                acc[mi][ni][r] = 0.f;

    const int T = (K + 31) / 32;

    auto load_tiles = [&](int t, int s) {
        int k0 = t * 32;
        uint32_t as_base = smem_u32(As + s * AS_ELE);
        uint32_t bs_base = smem_u32(Bs + s * BS_ELE);
        #pragma unroll
        for (int i = 0; i < 4; i++) {
            int f = tid + i * 256;
            int row = f >> 3, kq = (f & 7) * 4;
            int gm = bm0 + row, gk = k0 + kq;
            int bytes = 0;
            const float* src = A;
            if (gm < M) {
                int rem = K - gk;
                if (rem > 0) { bytes = rem >= 4 ? 16 : rem * 4; src = A + (long)gm * lda + gk; }
            }
            cp16(as_base + (uint32_t)(row * AS_STRIDE + kq) * 4u, src, bytes);
        }
        #pragma unroll
        for (int i = 0; i < BN / 32; i++) {
            int f = tid + i * 256;
            int kr = f / (BN / 4), nq = (f % (BN / 4)) * 4;
            int gk = k0 + kr, gn = bn0 + nq;
            int bytes = 0;
            const float* src = B;
            if (gk < K && gn < N) { bytes = 16; src = B + (long)gk * ldb + gn; }
            cp16(bs_base + (uint32_t)(kr * BS_STRIDE + nq) * 4u, src, bytes);
        }
    };

    load_tiles(0, 0);
    cp_commit();
    if (T > 1) { load_tiles(1, 1); }
    cp_commit();

    for (int t = 0; t < T; t++) {
        if (t + 1 < T) cp_wait<1>(); else cp_wait<0>();
        __syncthreads();
        if (t + 2 < T) { load_tiles(t + 2, (t + 2) % STAGES); }
        cp_commit();
        const float* Asb = As + (t % STAGES) * AS_ELE;
        const float* Bsb = Bs + (t % STAGES) * BS_ELE;
        #pragma unroll
        for (int ks = 0; ks < 4; ks++) {
            unsigned af[4][4], bf[NFR][2];
            #pragma unroll
            for (int mi = 0; mi < 4; mi++) {
                const float* p = &Asb[(wm * 64 + mi * 16 + lr) * AS_STRIDE + ks * 8 + lc];
                af[mi][0] = __float_as_uint(p[0]);
                af[mi][1] = __float_as_uint(p[8 * AS_STRIDE]);
                af[mi][2] = __float_as_uint(p[4]);
                af[mi][3] = __float_as_uint(p[8 * AS_STRIDE + 4]);
            }
            #pragma unroll
            for (int ni = 0; ni < NFR; ni++) {
                const float* p = &Bsb[(ks * 8 + lc) * BS_STRIDE + wn * (BN / 4) + ni * 8 + lr];
                bf[ni][0] = __float_as_uint(p[0]);
                bf[ni][1] = __float_as_uint(p[4 * BS_STRIDE]);
            }
            #pragma unroll
            for (int mi = 0; mi < 4; mi++)
                #pragma unroll
                for (int ni = 0; ni < NFR; ni++)
                    mma_tf32(acc[mi][ni], af[mi], bf[ni]);
        }
        __syncthreads();
    }

    #pragma unroll
    for (int mi = 0; mi < 4; mi++) {
        #pragma unroll
        for (int ni = 0; ni < NFR; ni++) {
            int r0 = bm0 + wm * 64 + mi * 16 + lr;
            int c0 = bn0 + wn * (BN / 4) + ni * 8 + lc * 2;
            float b0 = 0.f, b1 = 0.f;
            if (bias) {
                if (c0 < N)     b0 = bias[c0];
                if (c0 + 1 < N) b1 = bias[c0 + 1];
            }
            #pragma unroll
            for (int rr = 0; rr < 2; rr++) {
                int rw = r0 + rr * 8;
                if (rw < M) {
                    float v0 = alpha * acc[mi][ni][rr * 2]     + b0;
                    float v1 = alpha * acc[mi][ni][rr * 2 + 1] + b1;
                    if (round_out) { v0 = f_tf32(v0); v1 = f_tf32(v1); }
                    if (c0 < N)     C[(long)rw * ldc + c0]     = v0;
                    if (c0 + 1 < N) C[(long)rw * ldc + c0 + 1] = v1;
                }
            }
        }
    }
}

// =====================================================================
// Fused flash attention: S = scale*Q K^T, online softmax, O = P V.
// Grid (9 q-tiles, 200 bh). 256 threads; warp w owns rows [w*16, w*16+16).
// smem: Q[128x132] + 2 stages of (K[64x132], V[64x132]); P aliases consumed
// K stage as [128x66].
// =====================================================================
#define FA_QELE  (128 * 132)       // 16896
#define FA_KVELE (64 * 132)        // 8448 per K or V
#define FA_SMEM  ((FA_QELE + 2 * 2 * FA_KVELE) * 4)   // 202752 bytes
#define FA_T     17                // ceil(1025/64)

__global__ void __launch_bounds__(256, 1)
flash_attn(const float* __restrict__ qkv, float* __restrict__ Og)
{
    extern __shared__ float fs[];
    float* Qs = fs;
    const int tid = threadIdx.x, w = tid >> 5, lane = tid & 31;
    const int lr = lane >> 2, lc = lane & 3;
    const int qt = blockIdx.x, bh = blockIdx.y;
    const int b = bh / H_HEADS, h = bh - b * H_HEADS;
    const float scale = 0.088388347648318447f;   // 1/sqrt(128)

    const float* qbase = qkv + (size_t)b * N_TOK * (3 * C_DIM) + h * D_HEAD;

    // ---- load Q tile (128 x 128) ----
    {
        uint32_t qsm = smem_u32(Qs);
        #pragma unroll
        for (int i = 0; i < 16; i++) {
            int id = tid + i * 256;            // 0..4095
            int r = id >> 5, kc = id & 31;
            int q = qt * 128 + r;
            const float* src = qbase; int bytes = 0;
            if (q < N_TOK) { src = qbase + (size_t)q * (3 * C_DIM) + kc * 4; bytes = 16; }
            cp16(qsm + (uint32_t)(r * 132 + kc * 4) * 4u, src, bytes);
        }
    }
    auto load_kv = [&](int t, int s) {
        float* Ks = fs + FA_QELE + s * 2 * FA_KVELE;
        float* Vs = Ks + FA_KVELE;
        uint32_t ksm = smem_u32(Ks), vsm = smem_u32(Vs);
        #pragma unroll
        for (int i = 0; i < 8; i++) {
            int id = tid + i * 256;            // 0..2047
            int r = id >> 5, kc = id & 31;
            int kv = t * 64 + r;
            const float* srck = qbase; const float* srcv = qbase; int bytes = 0;
            if (kv < N_TOK) {
                srck = qbase + (size_t)kv * (3 * C_DIM) + C_DIM + kc * 4;
                srcv = qbase + (size_t)kv * (3 * C_DIM) + 2 * C_DIM + kc * 4;
                bytes = 16;
            }
            cp16(ksm + (uint32_t)(r * 132 + kc * 4) * 4u, srck, bytes);
            cp16(vsm + (uint32_t)(r * 132 + kc * 4) * 4u, srcv, bytes);
        }
    };
    load_kv(0, 0);
    cp_commit();

    float o[16][4];
    #pragma unroll
    for (int ni = 0; ni < 16; ni++)
        #pragma unroll
        for (int r = 0; r < 4; r++) o[ni][r] = 0.f;
    float m0 = -1e30f, m1 = -1e30f, l0 = 0.f, l1 = 0.f;

    for (int t = 0; t < FA_T; t++) {
        int s = t & 1;
        cp_wait<0>();
        __syncthreads();
        if (t + 1 < FA_T) load_kv(t + 1, s ^ 1);
        cp_commit();

        float* Ks = fs + FA_QELE + s * 2 * FA_KVELE;
        float* Vs = Ks + FA_KVELE;

        // ---- S = Q K^T (per warp: 16 x 64, k = 128) ----
        float sa[8][4];
        #pragma unroll
        for (int ni = 0; ni < 8; ni++)
            #pragma unroll
            for (int r = 0; r < 4; r++) sa[ni][r] = 0.f;

        #pragma unroll
        for (int ks = 0; ks < 16; ks++) {
            unsigned a[4], bb[8][2];
            const float* pa = &Qs[(w * 16 + lr) * 132 + ks * 8 + lc];
            a[0] = __float_as_uint(pa[0]);
            a[1] = __float_as_uint(pa[8 * 132]);
            a[2] = __float_as_uint(pa[4]);
            a[3] = __float_as_uint(pa[8 * 132 + 4]);
            #pragma unroll
            for (int ni = 0; ni < 8; ni++) {
                const float* pb = &Ks[(ni * 8 + lr) * 132 + ks * 8 + lc];
                bb[ni][0] = __float_as_uint(pb[0]);
                bb[ni][1] = __float_as_uint(pb[4]);
            }
            #pragma unroll
            for (int ni = 0; ni < 8; ni++) mma_tf32(sa[ni], a, bb[ni]);
        }

        // ---- scale + mask ----
        #pragma unroll
        for (int ni = 0; ni < 8; ni++)
            #pragma unroll
            for (int r = 0; r < 4; r++) sa[ni][r] *= scale;
        if (t == FA_T - 1) {
            #pragma unroll
            for (int ni = 0; ni < 8; ni++) {
                int col = t * 64 + ni * 8 + 2 * lc;
                if (col >= N_TOK)     { sa[ni][0] = -1e30f; sa[ni][2] = -1e30f; }
                if (col + 1 >= N_TOK) { sa[ni][1] = -1e30f; sa[ni][3] = -1e30f; }
            }
        }

        // ---- online softmax (rows lr, lr+8 of warp block) ----
        float tm0 = -1e30f, tm1 = -1e30f;
        #pragma unroll
        for (int ni = 0; ni < 8; ni++) {
            tm0 = fmaxf(tm0, fmaxf(sa[ni][0], sa[ni][1]));
            tm1 = fmaxf(tm1, fmaxf(sa[ni][2], sa[ni][3]));
        }
        tm0 = fmaxf(tm0, __shfl_xor_sync(0xffffffffu, tm0, 1));
        tm0 = fmaxf(tm0, __shfl_xor_sync(0xffffffffu, tm0, 2));
        tm1 = fmaxf(tm1, __shfl_xor_sync(0xffffffffu, tm1, 1));
        tm1 = fmaxf(tm1, __shfl_xor_sync(0xffffffffu, tm1, 2));
        float mn0 = fmaxf(m0, tm0), mn1 = fmaxf(m1, tm1);
        float f0 = __expf(m0 - mn0), f1 = __expf(m1 - mn1);
        m0 = mn0; m1 = mn1;
        float rs0 = 0.f, rs1 = 0.f;
        #pragma unroll
        for (int ni = 0; ni < 8; ni++) {
            sa[ni][0] = __expf(sa[ni][0] - mn0); rs0 += sa[ni][0];
            sa[ni][1] = __expf(sa[ni][1] - mn0); rs0 += sa[ni][1];
            sa[ni][2] = __expf(sa[ni][2] - mn1); rs1 += sa[ni][2];
            sa[ni][3] = __expf(sa[ni][3] - mn1); rs1 += sa[ni][3];
        }
        rs0 += __shfl_xor_sync(0xffffffffu, rs0, 1);
        rs0 += __shfl_xor_sync(0xffffffffu, rs0, 2);
        rs1 += __shfl_xor_sync(0xffffffffu, rs1, 1);
        rs1 += __shfl_xor_sync(0xffffffffu, rs1, 2);
        l0 = l0 * f0 + rs0;
        l1 = l1 * f1 + rs1;
        #pragma unroll
        for (int ni = 0; ni < 16; ni++) {
            o[ni][0] *= f0; o[ni][1] *= f0;
            o[ni][2] *= f1; o[ni][3] *= f1;
        }

        // ---- write P (tf32-rounded) into K-stage alias [128 x 66] ----
        __syncthreads();                      // all warps done reading Ks
        float* Ps = Ks;
        {
            int r0 = w * 16 + lr;
            #pragma unroll
            for (int ni = 0; ni < 8; ni++) {
                float2 v0 = make_float2(f_tf32(sa[ni][0]), f_tf32(sa[ni][1]));
                float2 v1 = make_float2(f_tf32(sa[ni][2]), f_tf32(sa[ni][3]));
                *reinterpret_cast<float2*>(&Ps[r0 * 66 + ni * 8 + 2 * lc]) = v0;
                *reinterpret_cast<float2*>(&Ps[(r0 + 8) * 66 + ni * 8 + 2 * lc]) = v1;
            }
        }
        __syncwarp();                         // own-warp P visibility

        // ---- O += P V (per warp: 16 x 128, k = 64) ----
        #pragma unroll
        for (int ks = 0; ks < 8; ks++) {
            unsigned a[4], bb[16][2];
            const float* pa = &Ps[(w * 16 + lr) * 66 + ks * 8 + lc];
            a[0] = __float_as_uint(pa[0]);
            a[1] = __float_as_uint(pa[8 * 66]);
            a[2] = __float_as_uint(pa[4]);
            a[3] = __float_as_uint(pa[8 * 66 + 4]);
            #pragma unroll
            for (int ni = 0; ni < 16; ni++) {
                const float* pb = &Vs[(ks * 8 + lc) * 132 + ni * 8 + lr];
                bb[ni][0] = __float_as_uint(pb[0]);
                bb[ni][1] = __float_as_uint(pb[4 * 132]);
            }
            #pragma unroll
            for (int ni = 0; ni < 16; ni++) mma_tf32(o[ni], a, bb[ni]);
        }
    }

    // ---- epilogue: O / l, rounded, to g_att [b*N+q][h*128+d] ----
    float i0 = 1.f / l0, i1 = 1.f / l1;
    int m0g = qt * 128 + w * 16 + lr, m1g = m0g + 8;
    if (m0g < N_TOK) {
        float* dst = Og + ((size_t)(b * N_TOK + m0g)) * C_DIM + h * D_HEAD;
        #pragma unroll
        for (int ni = 0; ni < 16; ni++) {
            float2 v = make_float2(f_tf32(o[ni][0] * i0), f_tf32(o[ni][1] * i0));
            *reinterpret_cast<float2*>(&dst[ni * 8 + 2 * lc]) = v;
        }
    }
    if (m1g < N_TOK) {
        float* dst = Og + ((size_t)(b * N_TOK + m1g)) * C_DIM + h * D_HEAD;
        #pragma unroll
        for (int ni = 0; ni < 16; ni++) {
            float2 v = make_float2(f_tf32(o[ni][2] * i1), f_tf32(o[ni][3] * i1));
            *reinterpret_cast<float2*>(&dst[ni * 8 + 2 * lc]) = v;
        }
    }
}

// ===================== pre/post-processing kernels =====================

__global__ void round_copy(const float* __restrict__ in, float* __restrict__ out, long n4)
{
    long i = (long)blockIdx.x * blockDim.x + threadIdx.x;
    long stride = (long)gridDim.x * blockDim.x;
    for (; i < n4; i += stride) {
        float4 v = reinterpret_cast<const float4*>(in)[i];
        v.x = f_tf32(v.x); v.y = f_tf32(v.y); v.z = f_tf32(v.z); v.w = f_tf32(v.w);
        reinterpret_cast<float4*>(out)[i] = v;
    }
}

// RMSNorm over full C for q and k segments of one qkv row, in place (tf32-rounded out).
__global__ void rmsnorm_qk(float* __restrict__ qkv,
                           const float* __restrict__ qw, const float* __restrict__ kw)
{
    float* row = qkv + (size_t)blockIdx.x * (3 * C_DIM);
    int tid = threadIdx.x;
    float sq = 0.f, sk = 0.f;
    for (int i = tid * 4; i < C_DIM; i += 256 * 4) {
        float4 q = *reinterpret_cast<const float4*>(row + i);
        float4 k = *reinterpret_cast<const float4*>(row + C_DIM + i);
        sq += q.x * q.x + q.y * q.y + q.z * q.z + q.w * q.w;
        sk += k.x * k.x + k.y * k.y + k.z * k.z + k.w * k.w;
    }
    #pragma unroll
    for (int o = 16; o; o >>= 1) {
        sq += __shfl_xor_sync(0xffffffffu, sq, o);
        sk += __shfl_xor_sync(0xffffffffu, sk, o);
    }
    __shared__ float s1[8], s2[8];
    int lane = tid & 31, warp = tid >> 5;
    if (lane == 0) { s1[warp] = sq; s2[warp] = sk; }
    __syncthreads();
    if (tid == 0) {
        float a = 0.f, b = 0.f;
        #pragma unroll
        for (int w = 0; w < 8; w++) { a += s1[w]; b += s2[w]; }
        s1[0] = rsqrtf(a / C_DIM + 1e-6f);
        s2[0] = rsqrtf(b / C_DIM + 1e-6f);
    }
    __syncthreads();
    float invq = s1[0], invk = s2[0];
    for (int i = tid * 4; i < C_DIM; i += 256 * 4) {
        float4 q = *reinterpret_cast<const float4*>(row + i);
        float4 k = *reinterpret_cast<const float4*>(row + C_DIM + i);
        q.x = f_tf32(q.x * invq * qw[i]);     q.y = f_tf32(q.y * invq * qw[i + 1]);
        q.z = f_tf32(q.z * invq * qw[i + 2]); q.w = f_tf32(q.w * invq * qw[i + 3]);
        k.x = f_tf32(k.x * invk * kw[i]);     k.y = f_tf32(k.y * invk * kw[i + 1]);
        k.z = f_tf32(k.z * invk * kw[i + 2]); k.w = f_tf32(k.w * invk * kw[i + 3]);
        *reinterpret_cast<float4*>(row + i) = q;
        *reinterpret_cast<float4*>(row + C_DIM + i) = k;
    }
}

extern "C" void kernel_launch(void* const* d_in, const int* in_sizes, int n_in,
                              void* d_out, int out_size)
{
    const float* x        = (const float*)d_in[0];
    const float* qkv_w    = (const float*)d_in[1];
    const float* qkv_b    = (const float*)d_in[2];
    const float* q_norm_w = (const float*)d_in[3];
    const float* k_norm_w = (const float*)d_in[4];
    const float* proj_w   = (const float*)d_in[5];
    const float* proj_b   = (const float*)d_in[6];
    float* out = (float*)d_out;

    float *qkvp, *attp, *xp, *wqkvp, *wprojp;
    cudaGetSymbolAddress((void**)&qkvp,  g_qkv);
    cudaGetSymbolAddress((void**)&attp,  g_att);
    cudaGetSymbolAddress((void**)&xp,    g_x);
    cudaGetSymbolAddress((void**)&wqkvp, g_wqkv);
    cudaGetSymbolAddress((void**)&wprojp,g_wproj);

    const int smem_big = 3 * (128 * 36 + 32 * 264) * (int)sizeof(float);   // 156672
    cudaFuncSetAttribute(gemm_tf32<256, false>, cudaFuncAttributeMaxDynamicSharedMemorySize, smem_big);
    cudaFuncSetAttribute(flash_attn, cudaFuncAttributeMaxDynamicSharedMemorySize, FA_SMEM);

    dim3 blk(256);

    // 0. Pre-round operands once
    round_copy<<<2048, 256>>>(x, xp, (long)M_ROWS * C_DIM / 4);
    round_copy<<<2048, 256>>>(qkv_w, wqkvp, (long)C_DIM * 3 * C_DIM / 4);
    round_copy<<<2048, 256>>>(proj_w, wprojp, (long)C_DIM * C_DIM / 4);

    // 1. QKV GEMM: [8200,3200] x [3200,9600] + bias -> g_qkv (rounded out)
    {
        int TM = (M_ROWS + 127) / 128;          // 65
        int TN = (3 * C_DIM + 255) / 256;       // 38
        gemm_tf32<256, false><<<dim3(TM * TN, 1, 1), blk, smem_big>>>(
            xp, wqkvp, qkv_b, qkvp, M_ROWS, 3 * C_DIM, C_DIM,
            C_DIM, 3 * C_DIM, 3 * C_DIM, 1.0f, 1, TM, TN);
    }

    // 2. RMSNorm q,k in place (rounded out)
    rmsnorm_qk<<<M_ROWS, blk>>>(qkvp, q_norm_w, k_norm_w);

    // 3-5. Fused flash attention -> g_att (rounded out)
    flash_attn<<<dim3(9, 200), blk, FA_SMEM>>>(qkvp, attp);

    // 6. Proj GEMM: [8200,3200] x [3200,3200] + bias -> out
    {
        int TM = (M_ROWS + 127) / 128;          // 65
        int TN = (C_DIM + 255) / 256;           // 13
        gemm_tf32<256, false><<<dim3(TM * TN, 1, 1), blk, smem_big>>>(
            attp, wprojp, proj_b, out, M_ROWS, C_DIM, C_DIM,
            C_DIM, C_DIM, C_DIM, 1.0f, 0, TM, TN);
    }
}

// round 6
// speedup vs baseline: 1.4083x; 1.0743x over previous
#include <cuda_runtime.h>
#include <cuda_bf16.h>
#include <math.h>
#include <stdint.h>

// Problem constants
#define H_HEADS 25
#define B_DIM   8
#define N_TOK   1025
#define C_DIM   3200
#define D_HEAD  128
#define M_ROWS  (B_DIM * N_TOK)   // 8200

// Scratch (device globals: allocation inside kernel_launch is forbidden)
__device__ float g_qkv[(size_t)M_ROWS * 3 * C_DIM];               // [8200, 9600]
__device__ float g_att[(size_t)M_ROWS * C_DIM];                   // [8200, 3200]
__device__ float g_x[(size_t)M_ROWS * C_DIM];                     // rounded copy of x
__device__ float g_wqkv[(size_t)C_DIM * 3 * C_DIM];               // rounded qkv_w
__device__ float g_wproj[(size_t)C_DIM * C_DIM];                  // rounded proj_w

__device__ __forceinline__ float f_tf32(float x) {
    float r;
    asm("cvt.rna.tf32.f32 %0, %1;" : "=f"(r) : "f"(x));
    return r;
}

__device__ __forceinline__ void cp16(uint32_t dst, const void* src, int bytes) {
    asm volatile("cp.async.cg.shared.global [%0], [%1], 16, %2;\n"
                 :: "r"(dst), "l"(src), "r"(bytes));
}
__device__ __forceinline__ void cp_commit() { asm volatile("cp.async.commit_group;\n" ::); }
template<int NN>
__device__ __forceinline__ void cp_wait() { asm volatile("cp.async.wait_group %0;\n" :: "n"(NN)); }

__device__ __forceinline__ uint32_t smem_u32(const void* p) {
    return (uint32_t)__cvta_generic_to_shared(p);
}

__device__ __forceinline__ void mma_tf32(float (&d)[4], const unsigned (&a)[4], const unsigned (&b)[2]) {
    asm volatile(
        "mma.sync.aligned.m16n8k8.row.col.f32.tf32.tf32.f32 "
        "{%0,%1,%2,%3}, {%4,%5,%6,%7}, {%8,%9}, {%0,%1,%2,%3};"
        : "+f"(d[0]), "+f"(d[1]), "+f"(d[2]), "+f"(d[3])
        : "r"(a[0]), "r"(a[1]), "r"(a[2]), "r"(a[3]), "r"(b[0]), "r"(b[1]));
}

// =====================================================================
// Batched TF32 GEMM, operands PRE-ROUNDED to tf32 in gmem.
// Used for QKV and Proj GEMMs.
// =====================================================================
template<int BN, bool TRANS_B>
__global__ void __launch_bounds__(256, (BN == 256) ? 1 : 2)
gemm_tf32(const float* __restrict__ A, const float* __restrict__ B,
          const float* __restrict__ bias, float* __restrict__ C,
          int M, int N, int K,
          long lda, long ldb, long ldc,
          float alpha, int round_out, int TM, int TN)
{
    constexpr int NFR = BN / 32;
    constexpr int AS_STRIDE = 36;
    constexpr int BS_STRIDE = TRANS_B ? 36 : (BN + 8);
    constexpr int AS_ELE = 128 * AS_STRIDE;
    constexpr int BS_ELE = TRANS_B ? BN * 36 : 32 * (BN + 8);
    constexpr int STAGES = 3;

    extern __shared__ float sm[];
    float* As = sm;
    float* Bs = sm + STAGES * AS_ELE;

    // m-grouped rasterization
    int tm, tn;
    {
        const int GM = 16;
        int per = GM * TN;
        int g = blockIdx.x / per, r = blockIdx.x - g * per;
        int rows = TM - g * GM; if (rows > GM) rows = GM;
        tm = g * GM + r % rows;
        tn = r / rows;
    }
    const int bm0 = tm * 128;
    const int bn0 = tn * BN;

    const int tid = threadIdx.x;
    const int lane = tid & 31, warp = tid >> 5;
    const int wm = warp & 1, wn = warp >> 1;
    const int lr = lane >> 2, lc = lane & 3;

    float acc[4][NFR][4];
    #pragma unroll
    for (int mi = 0; mi < 4; mi++)
        #pragma unroll
        for (int ni = 0; ni < NFR; ni++)
            #pragma unroll
            for (int r = 0; r < 4; r++)
                acc[mi][ni][r] = 0.f;

    const int T = (K + 31) / 32;

    auto load_tiles = [&](int t, int s) {
        int k0 = t * 32;
        uint32_t as_base = smem_u32(As + s * AS_ELE);
        uint32_t bs_base = smem_u32(Bs + s * BS_ELE);
        #pragma unroll
        for (int i = 0; i < 4; i++) {
            int f = tid + i * 256;
            int row = f >> 3, kq = (f & 7) * 4;
            int gm = bm0 + row, gk = k0 + kq;
            int bytes = 0;
            const float* src = A;
            if (gm < M) {
                int rem = K - gk;
                if (rem > 0) { bytes = rem >= 4 ? 16 : rem * 4; src = A + (long)gm * lda + gk; }
            }
            cp16(as_base + (uint32_t)(row * AS_STRIDE + kq) * 4u, src, bytes);
        }
        #pragma unroll
        for (int i = 0; i < BN / 32; i++) {
            int f = tid + i * 256;
            int kr = f / (BN / 4), nq = (f % (BN / 4)) * 4;
            int gk = k0 + kr, gn = bn0 + nq;
            int bytes = 0;
            const float* src = B;
            if (gk < K && gn < N) { bytes = 16; src = B + (long)gk * ldb + gn; }
            cp16(bs_base + (uint32_t)(kr * BS_STRIDE + nq) * 4u, src, bytes);
        }
    };

    load_tiles(0, 0);
    cp_commit();
    if (T > 1) { load_tiles(1, 1); }
    cp_commit();

    for (int t = 0; t < T; t++) {
        if (t + 1 < T) cp_wait<1>(); else cp_wait<0>();
        __syncthreads();
        if (t + 2 < T) { load_tiles(t + 2, (t + 2) % STAGES); }
        cp_commit();
        const float* Asb = As + (t % STAGES) * AS_ELE;
        const float* Bsb = Bs + (t % STAGES) * BS_ELE;
        #pragma unroll
        for (int ks = 0; ks < 4; ks++) {
            unsigned af[4][4], bf[NFR][2];
            #pragma unroll
            for (int mi = 0; mi < 4; mi++) {
                const float* p = &Asb[(wm * 64 + mi * 16 + lr) * AS_STRIDE + ks * 8 + lc];
                af[mi][0] = __float_as_uint(p[0]);
                af[mi][1] = __float_as_uint(p[8 * AS_STRIDE]);
                af[mi][2] = __float_as_uint(p[4]);
                af[mi][3] = __float_as_uint(p[8 * AS_STRIDE + 4]);
            }
            #pragma unroll
            for (int ni = 0; ni < NFR; ni++) {
                const float* p = &Bsb[(ks * 8 + lc) * BS_STRIDE + wn * (BN / 4) + ni * 8 + lr];
                bf[ni][0] = __float_as_uint(p[0]);
                bf[ni][1] = __float_as_uint(p[4 * BS_STRIDE]);
            }
            #pragma unroll
            for (int mi = 0; mi < 4; mi++)
                #pragma unroll
                for (int ni = 0; ni < NFR; ni++)
                    mma_tf32(acc[mi][ni], af[mi], bf[ni]);
        }
        // no trailing __syncthreads: top-of-loop barrier already orders stage reuse
    }

    #pragma unroll
    for (int mi = 0; mi < 4; mi++) {
        #pragma unroll
        for (int ni = 0; ni < NFR; ni++) {
            int r0 = bm0 + wm * 64 + mi * 16 + lr;
            int c0 = bn0 + wn * (BN / 4) + ni * 8 + lc * 2;
            float b0 = 0.f, b1 = 0.f;
            if (bias) {
                if (c0 < N)     b0 = bias[c0];
                if (c0 + 1 < N) b1 = bias[c0 + 1];
            }
            #pragma unroll
            for (int rr = 0; rr < 2; rr++) {
                int rw = r0 + rr * 8;
                if (rw < M) {
                    float v0 = alpha * acc[mi][ni][rr * 2]     + b0;
                    float v1 = alpha * acc[mi][ni][rr * 2 + 1] + b1;
                    if (round_out) { v0 = f_tf32(v0); v1 = f_tf32(v1); }
                    if (c0 < N)     C[(long)rw * ldc + c0]     = v0;
                    if (c0 + 1 < N) C[(long)rw * ldc + c0 + 1] = v1;
                }
            }
        }
    }
}

// =====================================================================
// Fused flash attention v2: warp grid 4 (q-row groups of 32) x 2 (kv half).
// Each warp: S-tile 32x32 over its own kv half, private online softmax,
// PV 32x128 with P passed register->register via shfl (no smem P, 1 sync/tile).
// Final cross-half merge through smem (split-KV merge) once per CTA.
// smem: Q[128x132] + 2 stages of (K[64x132], V[64x132]).
// =====================================================================
#define FA_QELE  (128 * 132)       // 16896
#define FA_KVELE (64 * 132)        // 8448 per K or V
#define FA_SMEM  ((FA_QELE + 2 * 2 * FA_KVELE) * 4)   // 202752 bytes
#define FA_T     17                // ceil(1025/64)

__global__ void __launch_bounds__(256, 1)
flash_attn(const float* __restrict__ qkv, float* __restrict__ Og)
{
    extern __shared__ float fs[];
    float* Qs = fs;
    const int tid = threadIdx.x, w = tid >> 5, lane = tid & 31;
    const int wr = w >> 1, wc = w & 1;        // 4 q-row groups x 2 kv halves
    const int lr = lane >> 2, lc = lane & 3;
    const int qt = blockIdx.x, bh = blockIdx.y;
    const int b = bh / H_HEADS, h = bh - b * H_HEADS;
    const float scale = 0.088388347648318447f;   // 1/sqrt(128)

    const float* qbase = qkv + (size_t)b * N_TOK * (3 * C_DIM) + h * D_HEAD;

    // ---- load Q tile (128 x 128) ----
    {
        uint32_t qsm = smem_u32(Qs);
        #pragma unroll
        for (int i = 0; i < 16; i++) {
            int id = tid + i * 256;            // 0..4095
            int r = id >> 5, kc = id & 31;
            int q = qt * 128 + r;
            const float* src = qbase; int bytes = 0;
            if (q < N_TOK) { src = qbase + (size_t)q * (3 * C_DIM) + kc * 4; bytes = 16; }
            cp16(qsm + (uint32_t)(r * 132 + kc * 4) * 4u, src, bytes);
        }
    }
    auto load_kv = [&](int t, int s) {
        float* Ks = fs + FA_QELE + s * 2 * FA_KVELE;
        float* Vs = Ks + FA_KVELE;
        uint32_t ksm = smem_u32(Ks), vsm = smem_u32(Vs);
        #pragma unroll
        for (int i = 0; i < 8; i++) {
            int id = tid + i * 256;            // 0..2047
            int r = id >> 5, kc = id & 31;
            int kv = t * 64 + r;
            const float* srck = qbase; const float* srcv = qbase; int bytes = 0;
            if (kv < N_TOK) {
                srck = qbase + (size_t)kv * (3 * C_DIM) + C_DIM + kc * 4;
                srcv = qbase + (size_t)kv * (3 * C_DIM) + 2 * C_DIM + kc * 4;
                bytes = 16;
            }
            cp16(ksm + (uint32_t)(r * 132 + kc * 4) * 4u, srck, bytes);
            cp16(vsm + (uint32_t)(r * 132 + kc * 4) * 4u, srcv, bytes);
        }
    };
    load_kv(0, 0);
    cp_commit();

    // O accumulators: rows wr*32 + mi*16 + {lr, lr+8}, cols ni*8 + {2lc, 2lc+1}
    float o[2][16][4];
    #pragma unroll
    for (int mi = 0; mi < 2; mi++)
        #pragma unroll
        for (int ni = 0; ni < 16; ni++)
            #pragma unroll
            for (int r = 0; r < 4; r++) o[mi][ni][r] = 0.f;
    // per-lane row stats: j = mi*2 + half  (half 0: row lr, 1: row lr+8)
    float mrow[4] = {-1e30f, -1e30f, -1e30f, -1e30f};
    float lrow[4] = {0.f, 0.f, 0.f, 0.f};

    for (int t = 0; t < FA_T; t++) {
        int s = t & 1;
        cp_wait<0>();
        __syncthreads();
        if (t + 1 < FA_T) load_kv(t + 1, s ^ 1);
        cp_commit();

        float* Ks = fs + FA_QELE + s * 2 * FA_KVELE;
        float* Vs = Ks + FA_KVELE;

        // ---- S = Q K^T (warp: 32 q-rows x 32 kv of its half, k = 128) ----
        float sa[2][4][4];
        #pragma unroll
        for (int mi = 0; mi < 2; mi++)
            #pragma unroll
            for (int ni = 0; ni < 4; ni++)
                #pragma unroll
                for (int r = 0; r < 4; r++) sa[mi][ni][r] = 0.f;

        #pragma unroll
        for (int ks = 0; ks < 16; ks++) {
            unsigned a[2][4], bb[4][2];
            #pragma unroll
            for (int mi = 0; mi < 2; mi++) {
                const float* pa = &Qs[(wr * 32 + mi * 16 + lr) * 132 + ks * 8 + lc];
                a[mi][0] = __float_as_uint(pa[0]);
                a[mi][1] = __float_as_uint(pa[8 * 132]);
                a[mi][2] = __float_as_uint(pa[4]);
                a[mi][3] = __float_as_uint(pa[8 * 132 + 4]);
            }
            #pragma unroll
            for (int ni = 0; ni < 4; ni++) {
                const float* pb = &Ks[(wc * 32 + ni * 8 + lr) * 132 + ks * 8 + lc];
                bb[ni][0] = __float_as_uint(pb[0]);
                bb[ni][1] = __float_as_uint(pb[4]);
            }
            #pragma unroll
            for (int mi = 0; mi < 2; mi++)
                #pragma unroll
                for (int ni = 0; ni < 4; ni++)
                    mma_tf32(sa[mi][ni], a[mi], bb[ni]);
        }

        // ---- scale + mask ----
        #pragma unroll
        for (int mi = 0; mi < 2; mi++)
            #pragma unroll
            for (int ni = 0; ni < 4; ni++)
                #pragma unroll
                for (int r = 0; r < 4; r++) sa[mi][ni][r] *= scale;
        if (t == FA_T - 1) {
            #pragma unroll
            for (int ni = 0; ni < 4; ni++) {
                int col = t * 64 + wc * 32 + ni * 8 + 2 * lc;
                if (col >= N_TOK) {
                    #pragma unroll
                    for (int mi = 0; mi < 2; mi++) { sa[mi][ni][0] = -1e30f; sa[mi][ni][2] = -1e30f; }
                }
                if (col + 1 >= N_TOK) {
                    #pragma unroll
                    for (int mi = 0; mi < 2; mi++) { sa[mi][ni][1] = -1e30f; sa[mi][ni][3] = -1e30f; }
                }
            }
        }

        // ---- online softmax (4 row-stats per lane, warp-local) ----
        float tm[4] = {-1e30f, -1e30f, -1e30f, -1e30f};
        #pragma unroll
        for (int mi = 0; mi < 2; mi++)
            #pragma unroll
            for (int ni = 0; ni < 4; ni++) {
                tm[mi * 2 + 0] = fmaxf(tm[mi * 2 + 0], fmaxf(sa[mi][ni][0], sa[mi][ni][1]));
                tm[mi * 2 + 1] = fmaxf(tm[mi * 2 + 1], fmaxf(sa[mi][ni][2], sa[mi][ni][3]));
            }
        #pragma unroll
        for (int j = 0; j < 4; j++) {
            tm[j] = fmaxf(tm[j], __shfl_xor_sync(0xffffffffu, tm[j], 1));
            tm[j] = fmaxf(tm[j], __shfl_xor_sync(0xffffffffu, tm[j], 2));
        }
        float fj[4];
        #pragma unroll
        for (int j = 0; j < 4; j++) {
            float mn = fmaxf(mrow[j], tm[j]);
            fj[j] = __expf(mrow[j] - mn);
            mrow[j] = mn;
        }
        float rs[4] = {0.f, 0.f, 0.f, 0.f};
        #pragma unroll
        for (int mi = 0; mi < 2; mi++)
            #pragma unroll
            for (int ni = 0; ni < 4; ni++) {
                sa[mi][ni][0] = __expf(sa[mi][ni][0] - mrow[mi * 2]);     rs[mi * 2] += sa[mi][ni][0];
                sa[mi][ni][1] = __expf(sa[mi][ni][1] - mrow[mi * 2]);     rs[mi * 2] += sa[mi][ni][1];
                sa[mi][ni][2] = __expf(sa[mi][ni][2] - mrow[mi * 2 + 1]); rs[mi * 2 + 1] += sa[mi][ni][2];
                sa[mi][ni][3] = __expf(sa[mi][ni][3] - mrow[mi * 2 + 1]); rs[mi * 2 + 1] += sa[mi][ni][3];
            }
        #pragma unroll
        for (int j = 0; j < 4; j++) {
            rs[j] += __shfl_xor_sync(0xffffffffu, rs[j], 1);
            rs[j] += __shfl_xor_sync(0xffffffffu, rs[j], 2);
            lrow[j] = lrow[j] * fj[j] + rs[j];
        }
        #pragma unroll
        for (int mi = 0; mi < 2; mi++)
            #pragma unroll
            for (int ni = 0; ni < 16; ni++) {
                o[mi][ni][0] *= fj[mi * 2];     o[mi][ni][1] *= fj[mi * 2];
                o[mi][ni][2] *= fj[mi * 2 + 1]; o[mi][ni][3] *= fj[mi * 2 + 1];
            }
        // round P to tf32 (consistent numerics with unfused path)
        #pragma unroll
        for (int mi = 0; mi < 2; mi++)
            #pragma unroll
            for (int ni = 0; ni < 4; ni++)
                #pragma unroll
                for (int r = 0; r < 4; r++) sa[mi][ni][r] = f_tf32(sa[mi][ni][r]);

        // ---- O += P V  (k = 32 own kv; P a-frags from sa via shfl) ----
        const int src0 = lr * 4 + (lc >> 1);
        const int src1 = src0 + 2;
        const bool odd = (lc & 1);
        #pragma unroll
        for (int ks = 0; ks < 4; ks++) {
            unsigned a[2][4];
            #pragma unroll
            for (int mi = 0; mi < 2; mi++) {
                float v00 = __shfl_sync(0xffffffffu, sa[mi][ks][0], src0);
                float v01 = __shfl_sync(0xffffffffu, sa[mi][ks][1], src0);
                float v10 = __shfl_sync(0xffffffffu, sa[mi][ks][2], src0);
                float v11 = __shfl_sync(0xffffffffu, sa[mi][ks][3], src0);
                float w00 = __shfl_sync(0xffffffffu, sa[mi][ks][0], src1);
                float w01 = __shfl_sync(0xffffffffu, sa[mi][ks][1], src1);
                float w10 = __shfl_sync(0xffffffffu, sa[mi][ks][2], src1);
                float w11 = __shfl_sync(0xffffffffu, sa[mi][ks][3], src1);
                a[mi][0] = __float_as_uint(odd ? v01 : v00);
                a[mi][1] = __float_as_uint(odd ? v11 : v10);
                a[mi][2] = __float_as_uint(odd ? w01 : w00);
                a[mi][3] = __float_as_uint(odd ? w11 : w10);
            }
            #pragma unroll
            for (int ni = 0; ni < 16; ni++) {
                unsigned bb[2];
                const float* pb = &Vs[(wc * 32 + ks * 8 + lc) * 132 + ni * 8 + lr];
                bb[0] = __float_as_uint(pb[0]);
                bb[1] = __float_as_uint(pb[4 * 132]);
                mma_tf32(o[0][ni], a[0], bb);
                mma_tf32(o[1][ni], a[1], bb);
            }
        }
    }

    // ---- cross-half merge (split-KV): wc=1 publishes, wc=0 merges & writes ----
    __syncthreads();                 // all compute done; Qs reusable as merge buffer
    if (wc == 1) {
        #pragma unroll
        for (int mi = 0; mi < 2; mi++) {
            int r0 = wr * 32 + mi * 16 + lr;
            #pragma unroll
            for (int ni = 0; ni < 16; ni++) {
                *reinterpret_cast<float2*>(&Qs[r0 * 132 + ni * 8 + 2 * lc]) =
                    make_float2(o[mi][ni][0], o[mi][ni][1]);
                *reinterpret_cast<float2*>(&Qs[(r0 + 8) * 132 + ni * 8 + 2 * lc]) =
                    make_float2(o[mi][ni][2], o[mi][ni][3]);
            }
            if (lc == 0) {
                Qs[r0 * 132 + 128] = mrow[mi * 2];
                Qs[r0 * 132 + 129] = lrow[mi * 2];
                Qs[(r0 + 8) * 132 + 128] = mrow[mi * 2 + 1];
                Qs[(r0 + 8) * 132 + 129] = lrow[mi * 2 + 1];
            }
        }
    }
    __syncthreads();
    if (wc == 0) {
        #pragma unroll
        for (int mi = 0; mi < 2; mi++) {
            #pragma unroll
            for (int half = 0; half < 2; half++) {
                int r0 = wr * 32 + mi * 16 + lr + half * 8;
                int j = mi * 2 + half;
                float m1 = Qs[r0 * 132 + 128];
                float l1 = Qs[r0 * 132 + 129];
                float mm = fmaxf(mrow[j], m1);
                float f0 = __expf(mrow[j] - mm), f1 = __expf(m1 - mm);
                float ll = lrow[j] * f0 + l1 * f1;
                float inv = 1.f / ll;
                int rg = qt * 128 + r0;
                if (rg < N_TOK) {
                    float* dst = Og + ((size_t)(b * N_TOK + rg)) * C_DIM + h * D_HEAD;
                    #pragma unroll
                    for (int ni = 0; ni < 16; ni++) {
                        float2 o1 = *reinterpret_cast<float2*>(&Qs[r0 * 132 + ni * 8 + 2 * lc]);
                        float v0 = (o[mi][ni][half * 2]     * f0 + o1.x * f1) * inv;
                        float v1 = (o[mi][ni][half * 2 + 1] * f0 + o1.y * f1) * inv;
                        *reinterpret_cast<float2*>(&dst[ni * 8 + 2 * lc]) =
                            make_float2(f_tf32(v0), f_tf32(v1));
                    }
                }
            }
        }
    }
}

// ===================== pre/post-processing kernels =====================

__global__ void round_copy(const float* __restrict__ in, float* __restrict__ out, long n4)
{
    long i = (long)blockIdx.x * blockDim.x + threadIdx.x;
    long stride = (long)gridDim.x * blockDim.x;
    for (; i < n4; i += stride) {
        float4 v = reinterpret_cast<const float4*>(in)[i];
        v.x = f_tf32(v.x); v.y = f_tf32(v.y); v.z = f_tf32(v.z); v.w = f_tf32(v.w);
        reinterpret_cast<float4*>(out)[i] = v;
    }
}

// RMSNorm over full C for q and k segments of one qkv row, in place (tf32-rounded out).
__global__ void rmsnorm_qk(float* __restrict__ qkv,
                           const float* __restrict__ qw, const float* __restrict__ kw)
{
    float* row = qkv + (size_t)blockIdx.x * (3 * C_DIM);
    int tid = threadIdx.x;
    float sq = 0.f, sk = 0.f;
    for (int i = tid * 4; i < C_DIM; i += 256 * 4) {
        float4 q = *reinterpret_cast<const float4*>(row + i);
        float4 k = *reinterpret_cast<const float4*>(row + C_DIM + i);
        sq += q.x * q.x + q.y * q.y + q.z * q.z + q.w * q.w;
        sk += k.x * k.x + k.y * k.y + k.z * k.z + k.w * k.w;
    }
    #pragma unroll
    for (int o = 16; o; o >>= 1) {
        sq += __shfl_xor_sync(0xffffffffu, sq, o);
        sk += __shfl_xor_sync(0xffffffffu, sk, o);
    }
    __shared__ float s1[8], s2[8];
    int lane = tid & 31, warp = tid >> 5;
    if (lane == 0) { s1[warp] = sq; s2[warp] = sk; }
    __syncthreads();
    if (tid == 0) {
        float a = 0.f, b = 0.f;
        #pragma unroll
        for (int w = 0; w < 8; w++) { a += s1[w]; b += s2[w]; }
        s1[0] = rsqrtf(a / C_DIM + 1e-6f);
        s2[0] = rsqrtf(b / C_DIM + 1e-6f);
    }
    __syncthreads();
    float invq = s1[0], invk = s2[0];
    for (int i = tid * 4; i < C_DIM; i += 256 * 4) {
        float4 q = *reinterpret_cast<const float4*>(row + i);
        float4 k = *reinterpret_cast<const float4*>(row + C_DIM + i);
        q.x = f_tf32(q.x * invq * qw[i]);     q.y = f_tf32(q.y * invq * qw[i + 1]);
        q.z = f_tf32(q.z * invq * qw[i + 2]); q.w = f_tf32(q.w * invq * qw[i + 3]);
        k.x = f_tf32(k.x * invk * kw[i]);     k.y = f_tf32(k.y * invk * kw[i + 1]);
        k.z = f_tf32(k.z * invk * kw[i + 2]); k.w = f_tf32(k.w * invk * kw[i + 3]);
        *reinterpret_cast<float4*>(row + i) = q;
        *reinterpret_cast<float4*>(row + C_DIM + i) = k;
    }
}

extern "C" void kernel_launch(void* const* d_in, const int* in_sizes, int n_in,
                              void* d_out, int out_size)
{
    const float* x        = (const float*)d_in[0];
    const float* qkv_w    = (const float*)d_in[1];
    const float* qkv_b    = (const float*)d_in[2];
    const float* q_norm_w = (const float*)d_in[3];
    const float* k_norm_w = (const float*)d_in[4];
    const float* proj_w   = (const float*)d_in[5];
    const float* proj_b   = (const float*)d_in[6];
    float* out = (float*)d_out;

    float *qkvp, *attp, *xp, *wqkvp, *wprojp;
    cudaGetSymbolAddress((void**)&qkvp,  g_qkv);
    cudaGetSymbolAddress((void**)&attp,  g_att);
    cudaGetSymbolAddress((void**)&xp,    g_x);
    cudaGetSymbolAddress((void**)&wqkvp, g_wqkv);
    cudaGetSymbolAddress((void**)&wprojp,g_wproj);

    const int smem_big = 3 * (128 * 36 + 32 * 264) * (int)sizeof(float);   // 156672
    cudaFuncSetAttribute(gemm_tf32<256, false>, cudaFuncAttributeMaxDynamicSharedMemorySize, smem_big);
    cudaFuncSetAttribute(flash_attn, cudaFuncAttributeMaxDynamicSharedMemorySize, FA_SMEM);

    dim3 blk(256);

    // 0. Pre-round operands once
    round_copy<<<2048, 256>>>(x, xp, (long)M_ROWS * C_DIM / 4);
    round_copy<<<2048, 256>>>(qkv_w, wqkvp, (long)C_DIM * 3 * C_DIM / 4);
    round_copy<<<2048, 256>>>(proj_w, wprojp, (long)C_DIM * C_DIM / 4);

    // 1. QKV GEMM: [8200,3200] x [3200,9600] + bias -> g_qkv (rounded out)
    {
        int TM = (M_ROWS + 127) / 128;          // 65
        int TN = (3 * C_DIM + 255) / 256;       // 38
        gemm_tf32<256, false><<<dim3(TM * TN, 1, 1), blk, smem_big>>>(
            xp, wqkvp, qkv_b, qkvp, M_ROWS, 3 * C_DIM, C_DIM,
            C_DIM, 3 * C_DIM, 3 * C_DIM, 1.0f, 1, TM, TN);
    }

    // 2. RMSNorm q,k in place (rounded out)
    rmsnorm_qk<<<M_ROWS, blk>>>(qkvp, q_norm_w, k_norm_w);

    // 3-5. Fused flash attention -> g_att (rounded out)
    flash_attn<<<dim3(9, 200), blk, FA_SMEM>>>(qkvp, attp);

    // 6. Proj GEMM: [8200,3200] x [3200,3200] + bias -> out
    {
        int TM = (M_ROWS + 127) / 128;          // 65
        int TN = (C_DIM + 255) / 256;           // 13
        gemm_tf32<256, false><<<dim3(TM * TN, 1, 1), blk, smem_big>>>(
            attp, wprojp, proj_b, out, M_ROWS, C_DIM, C_DIM,
            C_DIM, C_DIM, C_DIM, 1.0f, 0, TM, TN);
    }
}